// round 1
// baseline (speedup 1.0000x reference)
#include <cuda_runtime.h>
#include <cstdint>
#include <cstdio>

#define B_ 4
#define N_ 2048
#define C_ 1024
#define H_ 16
#define D_ 64
#define QKV_ELEMS (B_*H_*N_*D_)   // 8388608

// Scratch (allocation-free rule: __device__ globals)
__device__ float g_q[QKV_ELEMS];
__device__ float g_k[QKV_ELEMS];
__device__ float g_v[QKV_ELEMS];
__device__ float g_o[QKV_ELEMS];

// ---------------- packed f32x2 helpers (sm_100a) ----------------
__device__ __forceinline__ uint64_t pk2(float lo, float hi) {
    uint64_t r; asm("mov.b64 %0, {%1, %2};" : "=l"(r) : "f"(lo), "f"(hi)); return r;
}
__device__ __forceinline__ float2 up2(uint64_t v) {
    float2 r; asm("mov.b64 {%0, %1}, %2;" : "=f"(r.x), "=f"(r.y) : "l"(v)); return r;
}
__device__ __forceinline__ void ffma2(uint64_t& d, uint64_t a, uint64_t b) {
    asm("fma.rn.f32x2 %0, %1, %2, %0;" : "+l"(d) : "l"(a), "l"(b));
}
__device__ __forceinline__ void fmul2(uint64_t& d, uint64_t a) {
    asm("mul.rn.f32x2 %0, %0, %1;" : "+l"(d) : "l"(a));
}

// ================= Kernel 1: QKV GEMM + scatter =================
// C[8192,3072] = x[8192,1024] @ w_qkv[1024,3072], scattered into g_q/g_k/g_v [B,H,N,D]
__global__ __launch_bounds__(256) void qkv_gemm(const float* __restrict__ x,
                                                const float* __restrict__ w) {
    __shared__ float As[16][128];
    __shared__ float Bs[16][128];
    const int tid = threadIdx.x;
    const int tx = tid & 15, ty = tid >> 4;
    const int bn = blockIdx.x;   // 0..23
    const int bm = blockIdx.y;   // 0..63
    const int arow = tid >> 2;
    const int acol = (tid & 3) << 2;
    const int brow = tid >> 5;
    const int bcol = (tid & 31) << 2;
    const float* Ag = x + bm * 128 * C_;
    const float* Bg = w + bn * 128;

    uint64_t acc[8][4];
    #pragma unroll
    for (int i = 0; i < 8; i++) { acc[i][0] = 0; acc[i][1] = 0; acc[i][2] = 0; acc[i][3] = 0; }

    for (int kt = 0; kt < C_; kt += 16) {
        #pragma unroll
        for (int h = 0; h < 2; h++) {
            int r = arow + h * 64;
            float4 v = *(const float4*)(Ag + r * C_ + kt + acol);
            As[acol + 0][r] = v.x; As[acol + 1][r] = v.y;
            As[acol + 2][r] = v.z; As[acol + 3][r] = v.w;
        }
        #pragma unroll
        for (int h = 0; h < 2; h++) {
            int r = brow + h * 8;
            *(float4*)&Bs[r][bcol] = *(const float4*)(Bg + (kt + r) * 3072 + bcol);
        }
        __syncthreads();
        #pragma unroll
        for (int k = 0; k < 16; k++) {
            float4 b0 = *(float4*)&Bs[k][tx * 8];
            float4 b1 = *(float4*)&Bs[k][tx * 8 + 4];
            uint64_t bp0 = pk2(b0.x, b0.y), bp1 = pk2(b0.z, b0.w);
            uint64_t bp2 = pk2(b1.x, b1.y), bp3 = pk2(b1.z, b1.w);
            float4 a0 = *(float4*)&As[k][ty * 8];
            float4 a1 = *(float4*)&As[k][ty * 8 + 4];
            float a[8] = {a0.x, a0.y, a0.z, a0.w, a1.x, a1.y, a1.z, a1.w};
            #pragma unroll
            for (int i = 0; i < 8; i++) {
                uint64_t ap = pk2(a[i], a[i]);
                ffma2(acc[i][0], ap, bp0);
                ffma2(acc[i][1], ap, bp1);
                ffma2(acc[i][2], ap, bp2);
                ffma2(acc[i][3], ap, bp3);
            }
        }
        __syncthreads();
    }
    const int rowBase = bm * 128 + ty * 8;
    const int colBase = bn * 128 + tx * 8;
    #pragma unroll
    for (int i = 0; i < 8; i++) {
        int row = rowBase + i;
        int b = row >> 11, n = row & 2047;
        #pragma unroll
        for (int jp = 0; jp < 4; jp++) {
            int j = colBase + jp * 2;
            int which = j >> 10;
            int hh = (j >> 6) & 15;
            int d = j & 63;
            float* dst = which == 0 ? g_q : (which == 1 ? g_k : g_v);
            float2 v = up2(acc[i][jp]);
            *(float2*)(dst + (((b * H_ + hh) * N_ + n) * D_ + d)) = v;
        }
    }
}

// ================= Kernel 2: RMSNorm + RoPE (in place on g_q/g_k) =================
__global__ __launch_bounds__(256) void norm_rope(const float* __restrict__ qn_w,
                                                 const float* __restrict__ kn_w,
                                                 const float* __restrict__ fc,
                                                 const float* __restrict__ fs) {
    int gw = (blockIdx.x * 256 + threadIdx.x) >> 5;   // global warp = one head-row
    int lane = threadIdx.x & 31;
    const int half = B_ * H_ * N_;                    // 131072 rows each for q,k
    float* buf; const float* w; int r;
    if (gw < half) { buf = g_q; w = qn_w; r = gw; }
    else           { buf = g_k; w = kn_w; r = gw - half; }
    int n = r & (N_ - 1);
    float2 v = *(float2*)(buf + (size_t)r * D_ + lane * 2);
    float ss = v.x * v.x + v.y * v.y;
    #pragma unroll
    for (int o = 16; o; o >>= 1) ss += __shfl_xor_sync(0xffffffffu, ss, o);
    float rinv = rsqrtf(ss * (1.0f / D_) + 1e-6f);
    float a = v.x * rinv * w[lane * 2];
    float b = v.y * rinv * w[lane * 2 + 1];
    const float* fcp = fc + n * D_ + lane * 2;
    const float* fsp = fs + n * D_ + lane * 2;
    float c0 = fcp[0], c1 = fcp[1], s0 = fsp[0], s1 = fsp[1];
    // out[2i] = a*cos - b*sin ; out[2i+1] = b*cos + a*sin   (interleaved rotate_half)
    *(float2*)(buf + (size_t)r * D_ + lane * 2) = make_float2(a * c0 - b * s0, b * c1 + a * s1);
}

// ================= Kernel 3: flash attention (fp32, f32x2) =================
// grid (N/64, B*H); 256 threads; 64-row Q tile; 64-row K/V tiles; online softmax.
// smem tiles use an XOR chunk swizzle: chunk f of row r stored at f^(r>>2),
// which makes the strided K^T reads (8 lanes hitting 8 different rows at the
// same column) land on 8 distinct banks.
__global__ __launch_bounds__(256) void flash_attn() {
    extern __shared__ float smn[];
    float* Qs = smn;            // 64*64
    float* Ks = smn + 4096;     // 64*64
    float* Vs = smn + 8192;     // 64*64
    float* Ps = smn + 12288;    // 64 rows, stride 68
    const int tid = threadIdx.x;
    const int tx = tid & 15, ty = tid >> 4;
    const int qt = blockIdx.x, bh = blockIdx.y;
    const float* Qg = g_q + ((size_t)bh * N_ + qt * 64) * D_;
    const float* Kg = g_k + (size_t)bh * N_ * D_;
    const float* Vg = g_v + (size_t)bh * N_ * D_;

    #pragma unroll
    for (int it = 0; it < 4; it++) {
        int i = tid + it * 256;
        int rr = i >> 4, f = i & 15;
        *(float4*)(Qs + rr * 64 + ((f ^ (rr >> 2)) << 2)) = *(const float4*)(Qg + rr * 64 + f * 4);
    }

    float m_i[4], l_i[4];
    uint64_t o2[4][2];
    #pragma unroll
    for (int i = 0; i < 4; i++) { m_i[i] = -1e30f; l_i[i] = 0.f; o2[i][0] = 0; o2[i][1] = 0; }
    const float scale = 0.125f;   // D^-0.5

    for (int kt = 0; kt < N_ / 64; kt++) {
        __syncthreads();   // prev PV done (also orders the initial Q load)
        const float* kg = Kg + kt * 64 * D_;
        const float* vg = Vg + kt * 64 * D_;
        #pragma unroll
        for (int it = 0; it < 4; it++) {
            int i = tid + it * 256;
            int rr = i >> 4, f = i & 15;
            int off = rr * 64 + ((f ^ (rr >> 2)) << 2);
            *(float4*)(Ks + off) = *(const float4*)(kg + rr * 64 + f * 4);
            *(float4*)(Vs + off) = *(const float4*)(vg + rr * 64 + f * 4);
        }
        __syncthreads();

        // S = Q @ K^T  (pack f32x2 along the d-reduction: no dup-MOVs)
        uint64_t s2[4][4];
        #pragma unroll
        for (int i = 0; i < 4; i++)
            #pragma unroll
            for (int j = 0; j < 4; j++) s2[i][j] = 0;
        #pragma unroll
        for (int f = 0; f < 16; f++) {
            uint64_t qp[4][2], kp[4][2];
            #pragma unroll
            for (int i = 0; i < 4; i++) {
                float4 q = *(float4*)(Qs + (4 * ty + i) * 64 + ((f ^ ty) << 2));
                qp[i][0] = pk2(q.x, q.y); qp[i][1] = pk2(q.z, q.w);
            }
            #pragma unroll
            for (int j = 0; j < 4; j++) {
                float4 k = *(float4*)(Ks + (4 * tx + j) * 64 + ((f ^ tx) << 2));
                kp[j][0] = pk2(k.x, k.y); kp[j][1] = pk2(k.z, k.w);
            }
            #pragma unroll
            for (int i = 0; i < 4; i++)
                #pragma unroll
                for (int j = 0; j < 4; j++) {
                    ffma2(s2[i][j], qp[i][0], kp[j][0]);
                    ffma2(s2[i][j], qp[i][1], kp[j][1]);
                }
        }

        // online softmax (scale folded into exp argument; max commutes with +scale)
        #pragma unroll
        for (int i = 0; i < 4; i++) {
            float sv[4]; float mx = -1e30f;
            #pragma unroll
            for (int j = 0; j < 4; j++) {
                float2 t = up2(s2[i][j]); sv[j] = t.x + t.y; mx = fmaxf(mx, sv[j]);
            }
            mx = fmaxf(mx, __shfl_xor_sync(0xffffffffu, mx, 8));
            mx = fmaxf(mx, __shfl_xor_sync(0xffffffffu, mx, 4));
            mx = fmaxf(mx, __shfl_xor_sync(0xffffffffu, mx, 2));
            mx = fmaxf(mx, __shfl_xor_sync(0xffffffffu, mx, 1));
            float mnew = fmaxf(m_i[i], mx);
            float corr = __expf((m_i[i] - mnew) * scale);
            m_i[i] = mnew;
            float sum = 0.f; float p[4];
            #pragma unroll
            for (int j = 0; j < 4; j++) { p[j] = __expf((sv[j] - mnew) * scale); sum += p[j]; }
            sum += __shfl_xor_sync(0xffffffffu, sum, 8);
            sum += __shfl_xor_sync(0xffffffffu, sum, 4);
            sum += __shfl_xor_sync(0xffffffffu, sum, 2);
            sum += __shfl_xor_sync(0xffffffffu, sum, 1);
            l_i[i] = l_i[i] * corr + sum;
            uint64_t cp = pk2(corr, corr);
            fmul2(o2[i][0], cp); fmul2(o2[i][1], cp);
            *(float4*)(Ps + (4 * ty + i) * 68 + 4 * tx) = make_float4(p[0], p[1], p[2], p[3]);
        }
        __syncthreads();

        // O += P @ V  (pack f32x2 along output d; V chunks swizzled)
        #pragma unroll
        for (int c4 = 0; c4 < 16; c4++) {
            float4 pr[4];
            #pragma unroll
            for (int i = 0; i < 4; i++) pr[i] = *(float4*)(Ps + (4 * ty + i) * 68 + c4 * 4);
            #pragma unroll
            for (int u = 0; u < 4; u++) {
                int c = c4 * 4 + u;
                float4 vv = *(float4*)(Vs + c * 64 + ((tx ^ (c >> 2)) << 2));
                uint64_t v01 = pk2(vv.x, vv.y), v23 = pk2(vv.z, vv.w);
                #pragma unroll
                for (int i = 0; i < 4; i++) {
                    float pe = (u == 0) ? pr[i].x : (u == 1) ? pr[i].y : (u == 2) ? pr[i].z : pr[i].w;
                    uint64_t pd = pk2(pe, pe);
                    ffma2(o2[i][0], pd, v01);
                    ffma2(o2[i][1], pd, v23);
                }
            }
        }
    }

    float* Og = g_o + ((size_t)bh * N_ + qt * 64) * D_;
    #pragma unroll
    for (int i = 0; i < 4; i++) {
        float inv = 1.f / l_i[i];
        float2 a = up2(o2[i][0]), b = up2(o2[i][1]);
        *(float4*)(Og + (4 * ty + i) * 64 + 4 * tx) =
            make_float4(a.x * inv, a.y * inv, b.x * inv, b.y * inv);
    }
}

// ================= Kernel 4: output projection =================
// out[8192,1024] = O_att([B,H,N,D] -> [B,N,C] on the fly) @ w_proj + b_proj
__global__ __launch_bounds__(256) void proj_gemm(const float* __restrict__ w,
                                                 const float* __restrict__ bias,
                                                 float* __restrict__ out) {
    __shared__ float As[16][128];
    __shared__ float Bs[16][128];
    const int tid = threadIdx.x;
    const int tx = tid & 15, ty = tid >> 4;
    const int bn = blockIdx.x;   // 0..7
    const int bm = blockIdx.y;   // 0..63
    const int arow = tid >> 2;
    const int acol = (tid & 3) << 2;
    const int brow = tid >> 5;
    const int bcol = (tid & 31) << 2;

    uint64_t acc[8][4];
    #pragma unroll
    for (int i = 0; i < 8; i++) { acc[i][0] = 0; acc[i][1] = 0; acc[i][2] = 0; acc[i][3] = 0; }

    for (int kt = 0; kt < C_; kt += 16) {
        #pragma unroll
        for (int h = 0; h < 2; h++) {
            int rloc = arow + h * 64;
            int r = bm * 128 + rloc;
            int b = r >> 11, n = r & 2047;
            int k = kt + acol;
            int hh = k >> 6, d = k & 63;      // BK=16 | 64 -> whole float4 in one head
            float4 v = *(const float4*)(g_o + ((size_t)(b * H_ + hh) * N_ + n) * D_ + d);
            As[acol + 0][rloc] = v.x; As[acol + 1][rloc] = v.y;
            As[acol + 2][rloc] = v.z; As[acol + 3][rloc] = v.w;
        }
        #pragma unroll
        for (int h = 0; h < 2; h++) {
            int r = brow + h * 8;
            *(float4*)&Bs[r][bcol] = *(const float4*)(w + (kt + r) * C_ + bn * 128 + bcol);
        }
        __syncthreads();
        #pragma unroll
        for (int k = 0; k < 16; k++) {
            float4 b0 = *(float4*)&Bs[k][tx * 8];
            float4 b1 = *(float4*)&Bs[k][tx * 8 + 4];
            uint64_t bp0 = pk2(b0.x, b0.y), bp1 = pk2(b0.z, b0.w);
            uint64_t bp2 = pk2(b1.x, b1.y), bp3 = pk2(b1.z, b1.w);
            float4 a0 = *(float4*)&As[k][ty * 8];
            float4 a1 = *(float4*)&As[k][ty * 8 + 4];
            float a[8] = {a0.x, a0.y, a0.z, a0.w, a1.x, a1.y, a1.z, a1.w};
            #pragma unroll
            for (int i = 0; i < 8; i++) {
                uint64_t ap = pk2(a[i], a[i]);
                ffma2(acc[i][0], ap, bp0);
                ffma2(acc[i][1], ap, bp1);
                ffma2(acc[i][2], ap, bp2);
                ffma2(acc[i][3], ap, bp3);
            }
        }
        __syncthreads();
    }
    const int rowBase = bm * 128 + ty * 8;
    const int colBase = bn * 128 + tx * 8;
    #pragma unroll
    for (int i = 0; i < 8; i++) {
        #pragma unroll
        for (int jp = 0; jp < 4; jp++) {
            int j = colBase + jp * 2;
            float2 v = up2(acc[i][jp]);
            v.x += bias[j]; v.y += bias[j + 1];
            *(float2*)(out + (size_t)(rowBase + i) * C_ + j) = v;
        }
    }
}

// ================= launch =================
extern "C" void kernel_launch(void* const* d_in, const int* in_sizes, int n_in,
                              void* d_out, int out_size) {
    const float* x      = (const float*)d_in[0];
    const float* w_qkv  = (const float*)d_in[1];
    const float* w_proj = (const float*)d_in[2];
    const float* b_proj = (const float*)d_in[3];
    const float* qn_w   = (const float*)d_in[4];
    const float* kn_w   = (const float*)d_in[5];
    const float* fc     = (const float*)d_in[6];
    const float* fs     = (const float*)d_in[7];
    float* out = (float*)d_out;

    qkv_gemm<<<dim3(24, 64), 256>>>(x, w_qkv);
    norm_rope<<<32768, 256>>>(qn_w, kn_w, fc, fs);
    cudaFuncSetAttribute(flash_attn, cudaFuncAttributeMaxDynamicSharedMemorySize, 66560);
    flash_attn<<<dim3(32, 64), 256, 66560>>>();
    proj_gemm<<<dim3(8, 64), 256>>>(w_proj, b_proj, out);
}

// round 5
// speedup vs baseline: 1.2894x; 1.2894x over previous
#include <cuda_runtime.h>
#include <cstdint>

#define B_ 4
#define N_ 2048
#define C_ 1024
#define H_ 16
#define D_ 64
#define QKV_ELEMS (B_*H_*N_*D_)   // 8388608

// Scratch (allocation-free rule: __device__ globals)
__device__ float g_q[QKV_ELEMS];
__device__ float g_k[QKV_ELEMS];
__device__ float g_v[QKV_ELEMS];
__device__ float g_o[QKV_ELEMS];          // attention out, [B,N,C] layout
__device__ float g_wqkvT[3072 * 1024];    // w_qkv^T  [3072,1024]
__device__ float g_wprojT[1024 * 1024];   // w_proj^T [1024,1024]

// ---------------- helpers ----------------
__device__ __forceinline__ float tf32r(float x) {
    uint32_t u;
    asm("cvt.rna.tf32.f32 %0, %1;" : "=r"(u) : "f"(x));
    return __uint_as_float(u);
}
__device__ __forceinline__ void split2(float x, float& hi, float& lo) {
    hi = tf32r(x);
    lo = tf32r(x - hi);
}
__device__ __forceinline__ float exp2a(float x) {
    float r; asm("ex2.approx.f32 %0, %1;" : "=f"(r) : "f"(x)); return r;
}
// m16n8k8 tf32 mma: D += A*B. A: 4 regs, B: 2 regs, C/D: 4 f32.
__device__ __forceinline__ void mma8(float* d, const float* a, float b0, float b1) {
    asm volatile(
        "mma.sync.aligned.m16n8k8.row.col.f32.tf32.tf32.f32 "
        "{%0,%1,%2,%3}, {%4,%5,%6,%7}, {%8,%9}, {%0,%1,%2,%3};"
        : "+f"(d[0]), "+f"(d[1]), "+f"(d[2]), "+f"(d[3])
        : "r"(__float_as_uint(a[0])), "r"(__float_as_uint(a[1])),
          "r"(__float_as_uint(a[2])), "r"(__float_as_uint(a[3])),
          "r"(__float_as_uint(b0)),  "r"(__float_as_uint(b1)));
}
// 3xTF32: d += a*b with hi/lo splits (error-compensated)
__device__ __forceinline__ void mma8_3x(float* d, const float* ahi, const float* alo,
                                        float b0h, float b0l, float b1h, float b1l) {
    mma8(d, ahi, b0l, b1l);
    mma8(d, alo, b0h, b1h);
    mma8(d, ahi, b0h, b1h);
}

// ================= weight transpose (once): dst[c][r] = src[r][c] =================
__global__ __launch_bounds__(256) void transpose_w(const float* __restrict__ src,
                                                   float* __restrict__ dst,
                                                   int R, int Ccols) {
    __shared__ float t[32][33];
    int bx = blockIdx.x * 32, by = blockIdx.y * 32;
    int tx = threadIdx.x, ty = threadIdx.y;      // 32 x 8
    #pragma unroll
    for (int i = 0; i < 32; i += 8)
        t[ty + i][tx] = src[(size_t)(by + ty + i) * Ccols + bx + tx];
    __syncthreads();
    #pragma unroll
    for (int i = 0; i < 32; i += 8)
        dst[(size_t)(bx + ty + i) * R + by + tx] = t[tx][ty + i];
}

// ================= 3xTF32 mma.sync GEMM =================
// C[M,NN] = A[M,1024] @ BT[NN,1024]^T ; BM=BN=128, BK=32; 8 warps, 64x32 warp tiles.
// MODE 0: qkv (scatter into g_q/g_k/g_v [B,H,N,D]) ; MODE 1: proj (bias + out)
template<int MODE>
__global__ __launch_bounds__(256) void gemm_mma(const float* __restrict__ A,
                                                const float* __restrict__ BT,
                                                const float* __restrict__ bias,
                                                float* __restrict__ out) {
    __shared__ float As[128][36];   // stride 36: frag LDS bank = 4*gid+tig (all distinct)
    __shared__ float Bs[128][36];
    const int tid = threadIdx.x;
    const int wid = tid >> 5, lane = tid & 31;
    const int gid = lane >> 2, tig = lane & 3;
    const int wm = wid & 1, wn = wid >> 1;       // 2 x 4 warp grid
    const int bn = blockIdx.x, bm = blockIdx.y;

    float c[4][4][4];
    #pragma unroll
    for (int mf = 0; mf < 4; mf++)
        #pragma unroll
        for (int nf = 0; nf < 4; nf++)
            #pragma unroll
            for (int r = 0; r < 4; r++) c[mf][nf][r] = 0.f;

    const float* Ag = A + (size_t)(bm * 128) * 1024;
    const float* Bg = BT + (size_t)(bn * 128) * 1024;

    for (int kt = 0; kt < 32; kt++) {
        __syncthreads();
        #pragma unroll
        for (int it = 0; it < 4; it++) {
            int idx = tid + it * 256;
            int r = idx >> 3, f = (idx & 7) * 4;
            *(float4*)&As[r][f] = *(const float4*)(Ag + (size_t)r * 1024 + kt * 32 + f);
            *(float4*)&Bs[r][f] = *(const float4*)(Bg + (size_t)r * 1024 + kt * 32 + f);
        }
        __syncthreads();
        #pragma unroll
        for (int ks = 0; ks < 4; ks++) {
            const int k0 = ks * 8;
            float ah[4][4], al[4][4], bh[4][2], bl[4][2];
            #pragma unroll
            for (int mf = 0; mf < 4; mf++) {
                int r0 = wm * 64 + mf * 16 + gid;
                split2(As[r0][k0 + tig],     ah[mf][0], al[mf][0]);
                split2(As[r0 + 8][k0 + tig], ah[mf][1], al[mf][1]);
                split2(As[r0][k0 + tig + 4], ah[mf][2], al[mf][2]);
                split2(As[r0 + 8][k0 + tig + 4], ah[mf][3], al[mf][3]);
            }
            #pragma unroll
            for (int nf = 0; nf < 4; nf++) {
                int n0 = wn * 32 + nf * 8 + gid;
                split2(Bs[n0][k0 + tig],     bh[nf][0], bl[nf][0]);
                split2(Bs[n0][k0 + tig + 4], bh[nf][1], bl[nf][1]);
            }
            #pragma unroll
            for (int mf = 0; mf < 4; mf++)
                #pragma unroll
                for (int nf = 0; nf < 4; nf++)
                    mma8_3x(c[mf][nf], ah[mf], al[mf],
                            bh[nf][0], bl[nf][0], bh[nf][1], bl[nf][1]);
        }
    }

    // epilogue: thread holds rows (r0, r0+8), cols (gcol, gcol+1) per fragment
    #pragma unroll
    for (int mf = 0; mf < 4; mf++) {
        int r0g = bm * 128 + wm * 64 + mf * 16 + gid;
        int r1g = r0g + 8;
        #pragma unroll
        for (int nf = 0; nf < 4; nf++) {
            int gcol = bn * 128 + wn * 32 + nf * 8 + 2 * tig;
            if (MODE == 0) {
                int which = gcol >> 10, h = (gcol >> 6) & 15, d = gcol & 63;
                float* dst = which == 0 ? g_q : (which == 1 ? g_k : g_v);
                int b0i = r0g >> 11, n0i = r0g & 2047;
                int b1i = r1g >> 11, n1i = r1g & 2047;
                *(float2*)(dst + (((size_t)b0i * H_ + h) * N_ + n0i) * D_ + d) =
                    make_float2(c[mf][nf][0], c[mf][nf][1]);
                *(float2*)(dst + (((size_t)b1i * H_ + h) * N_ + n1i) * D_ + d) =
                    make_float2(c[mf][nf][2], c[mf][nf][3]);
            } else {
                float bx = bias[gcol], by = bias[gcol + 1];
                *(float2*)(out + (size_t)r0g * 1024 + gcol) =
                    make_float2(c[mf][nf][0] + bx, c[mf][nf][1] + by);
                *(float2*)(out + (size_t)r1g * 1024 + gcol) =
                    make_float2(c[mf][nf][2] + bx, c[mf][nf][3] + by);
            }
        }
    }
}

// ================= RMSNorm + RoPE (in place on g_q/g_k) =================
__global__ __launch_bounds__(256) void norm_rope(const float* __restrict__ qn_w,
                                                 const float* __restrict__ kn_w,
                                                 const float* __restrict__ fc,
                                                 const float* __restrict__ fs) {
    int gw = (blockIdx.x * 256 + threadIdx.x) >> 5;
    int lane = threadIdx.x & 31;
    const int half = B_ * H_ * N_;
    float* buf; const float* w; int r;
    if (gw < half) { buf = g_q; w = qn_w; r = gw; }
    else           { buf = g_k; w = kn_w; r = gw - half; }
    int n = r & (N_ - 1);
    float2 v = *(float2*)(buf + (size_t)r * D_ + lane * 2);
    float ss = v.x * v.x + v.y * v.y;
    #pragma unroll
    for (int o = 16; o; o >>= 1) ss += __shfl_xor_sync(0xffffffffu, ss, o);
    float rinv = rsqrtf(ss * (1.0f / D_) + 1e-6f);
    float a = v.x * rinv * w[lane * 2];
    float b = v.y * rinv * w[lane * 2 + 1];
    const float* fcp = fc + n * D_ + lane * 2;
    const float* fsp = fs + n * D_ + lane * 2;
    float c0 = fcp[0], c1 = fcp[1], s0 = fsp[0], s1 = fsp[1];
    *(float2*)(buf + (size_t)r * D_ + lane * 2) = make_float2(a * c0 - b * s0, b * c1 + a * s1);
}

// ================= flash attention via 3xTF32 mma.sync =================
// Grid (N/128, B*H). 256 thr, 8 warps; warp w owns q rows [qt*128+16w, +16).
// Q hi/lo fragments in registers; K/V tiles (64 keys) in smem; online softmax in
// m16n8 C-fragment layout; P re-enters PV via warp-private smem (fp32, split at load).
__global__ __launch_bounds__(256) void flash_attn_mma() {
    extern __shared__ float sm[];
    float* Ks = sm;                       // [64][68]  (key-major, d inner)
    float* Vs = sm + 64 * 68;             // [64][68]
    const int tid = threadIdx.x;
    const int wid = tid >> 5, lane = tid & 31;
    const int gid = lane >> 2, tig = lane & 3;
    float* Ps = sm + 2 * 64 * 68 + wid * 16 * 68;   // warp-private [16][68]

    const int qt = blockIdx.x, bh = blockIdx.y;
    const int qrow0 = qt * 128 + wid * 16;
    const float SC2 = 0.125f * 1.44269504088896f;   // scale * log2(e)

    // Q fragments hi/lo: cover q rows (gid, gid+8), cols (8ks+tig, +4)
    float aqh[8][4], aql[8][4];
    {
        const float* Qg = g_q + ((size_t)bh * N_ + qrow0) * D_;
        #pragma unroll
        for (int ks = 0; ks < 8; ks++) {
            split2(Qg[(size_t)gid * D_ + ks * 8 + tig],        aqh[ks][0], aql[ks][0]);
            split2(Qg[(size_t)(gid + 8) * D_ + ks * 8 + tig],  aqh[ks][1], aql[ks][1]);
            split2(Qg[(size_t)gid * D_ + ks * 8 + tig + 4],    aqh[ks][2], aql[ks][2]);
            split2(Qg[(size_t)(gid + 8) * D_ + ks * 8 + tig + 4], aqh[ks][3], aql[ks][3]);
        }
    }

    float m0 = -1e30f, m1 = -1e30f, l0 = 0.f, l1 = 0.f;
    float o[8][4];
    #pragma unroll
    for (int nf = 0; nf < 8; nf++)
        #pragma unroll
        for (int r = 0; r < 4; r++) o[nf][r] = 0.f;

    const float* Kg0 = g_k + (size_t)bh * N_ * D_;
    const float* Vg0 = g_v + (size_t)bh * N_ * D_;

    for (int kt = 0; kt < N_ / 64; kt++) {
        __syncthreads();   // K/V from previous tile fully consumed
        const float* Kg = Kg0 + kt * 64 * D_;
        const float* Vg = Vg0 + kt * 64 * D_;
        #pragma unroll
        for (int it = 0; it < 4; it++) {
            int idx = tid + it * 256;            // 0..1023
            int r = idx >> 4, f = (idx & 15) * 4;
            *(float4*)(Ks + r * 68 + f) = *(const float4*)(Kg + (size_t)r * D_ + f);
            *(float4*)(Vs + r * 68 + f) = *(const float4*)(Vg + (size_t)r * D_ + f);
        }
        __syncthreads();

        // S = Q @ K^T : B-frag = K[n=8nf+gid][k=8ks+tig] (conflict-free), split at load
        float s[8][4];
        #pragma unroll
        for (int nf = 0; nf < 8; nf++) {
            s[nf][0] = s[nf][1] = s[nf][2] = s[nf][3] = 0.f;
            const float* kb = Ks + (nf * 8 + gid) * 68;
            #pragma unroll
            for (int ks = 0; ks < 8; ks++) {
                float b0h, b0l, b1h, b1l;
                split2(kb[ks * 8 + tig],     b0h, b0l);
                split2(kb[ks * 8 + tig + 4], b1h, b1l);
                mma8_3x(s[nf], aqh[ks], aql[ks], b0h, b0l, b1h, b1l);
            }
        }

        // online softmax; rows r0 = gid (c0,c1), r1 = gid+8 (c2,c3)
        float mx0 = -1e30f, mx1 = -1e30f;
        #pragma unroll
        for (int nf = 0; nf < 8; nf++) {
            mx0 = fmaxf(mx0, fmaxf(s[nf][0], s[nf][1]));
            mx1 = fmaxf(mx1, fmaxf(s[nf][2], s[nf][3]));
        }
        mx0 = fmaxf(mx0, __shfl_xor_sync(0xffffffffu, mx0, 1));
        mx0 = fmaxf(mx0, __shfl_xor_sync(0xffffffffu, mx0, 2));
        mx1 = fmaxf(mx1, __shfl_xor_sync(0xffffffffu, mx1, 1));
        mx1 = fmaxf(mx1, __shfl_xor_sync(0xffffffffu, mx1, 2));
        float mn0 = fmaxf(m0, mx0), mn1 = fmaxf(m1, mx1);
        float corr0 = exp2a((m0 - mn0) * SC2), corr1 = exp2a((m1 - mn1) * SC2);
        m0 = mn0; m1 = mn1;

        float sum0 = 0.f, sum1 = 0.f;
        #pragma unroll
        for (int nf = 0; nf < 8; nf++) {
            float p0 = exp2a((s[nf][0] - mn0) * SC2);
            float p1 = exp2a((s[nf][1] - mn0) * SC2);
            float p2 = exp2a((s[nf][2] - mn1) * SC2);
            float p3 = exp2a((s[nf][3] - mn1) * SC2);
            sum0 += p0 + p1; sum1 += p2 + p3;
            int cc = nf * 8 + 2 * tig;
            Ps[gid * 68 + cc] = p0;       Ps[gid * 68 + cc + 1] = p1;
            Ps[(gid + 8) * 68 + cc] = p2; Ps[(gid + 8) * 68 + cc + 1] = p3;
        }
        sum0 += __shfl_xor_sync(0xffffffffu, sum0, 1);
        sum0 += __shfl_xor_sync(0xffffffffu, sum0, 2);
        sum1 += __shfl_xor_sync(0xffffffffu, sum1, 1);
        sum1 += __shfl_xor_sync(0xffffffffu, sum1, 2);
        l0 = l0 * corr0 + sum0;
        l1 = l1 * corr1 + sum1;
        #pragma unroll
        for (int nf = 0; nf < 8; nf++) {
            o[nf][0] *= corr0; o[nf][1] *= corr0;
            o[nf][2] *= corr1; o[nf][3] *= corr1;
        }
        __syncwarp();

        // O += P @ V : A-frag from warp-private Ps (split), B-frag = V[k][n] (split)
        #pragma unroll
        for (int ks = 0; ks < 8; ks++) {
            float aph[4], apl[4];
            split2(Ps[gid * 68 + ks * 8 + tig],           aph[0], apl[0]);
            split2(Ps[(gid + 8) * 68 + ks * 8 + tig],     aph[1], apl[1]);
            split2(Ps[gid * 68 + ks * 8 + tig + 4],       aph[2], apl[2]);
            split2(Ps[(gid + 8) * 68 + ks * 8 + tig + 4], aph[3], apl[3]);
            #pragma unroll
            for (int nf = 0; nf < 8; nf++) {
                float b0h, b0l, b1h, b1l;
                split2(Vs[(ks * 8 + tig) * 68 + nf * 8 + gid],     b0h, b0l);
                split2(Vs[(ks * 8 + tig + 4) * 68 + nf * 8 + gid], b1h, b1l);
                mma8_3x(o[nf], aph, apl, b0h, b0l, b1h, b1l);
            }
        }
    }

    // epilogue: write [B,N,C]
    float inv0 = 1.f / l0, inv1 = 1.f / l1;
    const int b = bh >> 4, h = bh & 15;
    float* Og = g_o + ((size_t)b * N_ + qrow0) * C_ + h * D_;
    #pragma unroll
    for (int nf = 0; nf < 8; nf++) {
        int cc = nf * 8 + 2 * tig;
        *(float2*)(Og + (size_t)gid * C_ + cc) =
            make_float2(o[nf][0] * inv0, o[nf][1] * inv0);
        *(float2*)(Og + (size_t)(gid + 8) * C_ + cc) =
            make_float2(o[nf][2] * inv1, o[nf][3] * inv1);
    }
}

// ================= launch =================
extern "C" void kernel_launch(void* const* d_in, const int* in_sizes, int n_in,
                              void* d_out, int out_size) {
    const float* x      = (const float*)d_in[0];
    const float* w_qkv  = (const float*)d_in[1];
    const float* w_proj = (const float*)d_in[2];
    const float* b_proj = (const float*)d_in[3];
    const float* qn_w   = (const float*)d_in[4];
    const float* kn_w   = (const float*)d_in[5];
    const float* fc     = (const float*)d_in[6];
    const float* fs     = (const float*)d_in[7];
    float* out = (float*)d_out;

    float* wqkvT;  cudaGetSymbolAddress((void**)&wqkvT,  g_wqkvT);
    float* wprojT; cudaGetSymbolAddress((void**)&wprojT, g_wprojT);
    float* oPtr;   cudaGetSymbolAddress((void**)&oPtr,   g_o);

    transpose_w<<<dim3(3072 / 32, 1024 / 32), dim3(32, 8)>>>(w_qkv, wqkvT, 1024, 3072);
    transpose_w<<<dim3(1024 / 32, 1024 / 32), dim3(32, 8)>>>(w_proj, wprojT, 1024, 1024);

    gemm_mma<0><<<dim3(24, 64), 256>>>(x, wqkvT, nullptr, nullptr);
    norm_rope<<<32768, 256>>>(qn_w, kn_w, fc, fs);

    const int attn_smem = (2 * 64 * 68 + 8 * 16 * 68) * 4;   // 69632 B
    cudaFuncSetAttribute(flash_attn_mma, cudaFuncAttributeMaxDynamicSharedMemorySize, attn_smem);
    flash_attn_mma<<<dim3(16, 64), 256, attn_smem>>>();

    gemm_mma<1><<<dim3(8, 64), 256>>>(oPtr, wprojT, b_proj, out);
}

// round 7
// speedup vs baseline: 1.6663x; 1.2924x over previous
#include <cuda_runtime.h>
#include <cstdint>

#define B_ 4
#define N_ 2048
#define C_ 1024
#define H_ 16
#define D_ 64
#define QKV_ELEMS (B_*H_*N_*D_)   // 8388608

// Scratch (allocation-free rule: __device__ globals)
__device__ float g_q[QKV_ELEMS];
__device__ float g_k[QKV_ELEMS];
__device__ float g_v[QKV_ELEMS];
__device__ float g_o[QKV_ELEMS];          // attention out, [B,N,C] layout
__device__ float g_wqkvT[3072 * 1024];    // w_qkv^T  [3072,1024]
__device__ float g_wprojT[1024 * 1024];   // w_proj^T [1024,1024]

// ---------------- helpers ----------------
__device__ __forceinline__ float tf32r(float x) {
    uint32_t u;
    asm("cvt.rna.tf32.f32 %0, %1;" : "=r"(u) : "f"(x));
    return __uint_as_float(u);
}
__device__ __forceinline__ void split2(float x, float& hi, float& lo) {
    hi = tf32r(x);
    lo = tf32r(x - hi);
}
__device__ __forceinline__ float exp2a(float x) {
    float r; asm("ex2.approx.f32 %0, %1;" : "=f"(r) : "f"(x)); return r;
}
// m16n8k8 tf32 mma: D += A*B. A: 4 regs, B: 2 regs, C/D: 4 f32.
__device__ __forceinline__ void mma8(float* d, const float* a, float b0, float b1) {
    asm volatile(
        "mma.sync.aligned.m16n8k8.row.col.f32.tf32.tf32.f32 "
        "{%0,%1,%2,%3}, {%4,%5,%6,%7}, {%8,%9}, {%0,%1,%2,%3};"
        : "+f"(d[0]), "+f"(d[1]), "+f"(d[2]), "+f"(d[3])
        : "r"(__float_as_uint(a[0])), "r"(__float_as_uint(a[1])),
          "r"(__float_as_uint(a[2])), "r"(__float_as_uint(a[3])),
          "r"(__float_as_uint(b0)),  "r"(__float_as_uint(b1)));
}
// 3xTF32: d += a*b with hi/lo splits (error-compensated), small terms first
__device__ __forceinline__ void mma8_3x(float* d, const float* ahi, const float* alo,
                                        float b0h, float b0l, float b1h, float b1l) {
    mma8(d, ahi, b0l, b1l);
    mma8(d, alo, b0h, b1h);
    mma8(d, ahi, b0h, b1h);
}

// ================= weight transpose (once): dst[c][r] = src[r][c] =================
__global__ __launch_bounds__(256) void transpose_w(const float* __restrict__ src,
                                                   float* __restrict__ dst,
                                                   int R, int Ccols) {
    __shared__ float t[32][33];
    int bx = blockIdx.x * 32, by = blockIdx.y * 32;
    int tx = threadIdx.x, ty = threadIdx.y;      // 32 x 8
    #pragma unroll
    for (int i = 0; i < 32; i += 8)
        t[ty + i][tx] = src[(size_t)(by + ty + i) * Ccols + bx + tx];
    __syncthreads();
    #pragma unroll
    for (int i = 0; i < 32; i += 8)
        dst[(size_t)(bx + ty + i) * R + by + tx] = t[tx][ty + i];
}

// ================= 3xTF32 mma.sync GEMM (splits hoisted to loader) =================
// C[M,NN] = A[M,1024] @ BT[NN,1024]^T ; BM=BN=128, BK=32; 8 warps, 64x32 warp tiles.
// MODE 0: qkv (scatter into g_q/g_k/g_v [B,H,N,D]) ; MODE 1: proj (bias + out)
template<int MODE>
__global__ __launch_bounds__(256, 2) void gemm_mma(const float* __restrict__ A,
                                                   const float* __restrict__ BT,
                                                   const float* __restrict__ bias,
                                                   float* __restrict__ out) {
    extern __shared__ float gsm[];
    float (*Ahi)[36] = (float(*)[36])gsm;         // stride 36: frag bank = 4*gid+tig
    float (*Alo)[36] = Ahi + 128;
    float (*Bhi)[36] = Alo + 128;
    float (*Blo)[36] = Bhi + 128;
    const int tid = threadIdx.x;
    const int wid = tid >> 5, lane = tid & 31;
    const int gid = lane >> 2, tig = lane & 3;
    const int wm = wid & 1, wn = wid >> 1;       // 2 x 4 warp grid
    const int bn = blockIdx.x, bm = blockIdx.y;

    float c[4][4][4];
    #pragma unroll
    for (int mf = 0; mf < 4; mf++)
        #pragma unroll
        for (int nf = 0; nf < 4; nf++)
            #pragma unroll
            for (int r = 0; r < 4; r++) c[mf][nf][r] = 0.f;

    const float* Ag = A + (size_t)(bm * 128) * 1024;
    const float* Bg = BT + (size_t)(bn * 128) * 1024;

    for (int kt = 0; kt < 32; kt++) {
        __syncthreads();
        #pragma unroll
        for (int it = 0; it < 4; it++) {
            int idx = tid + it * 256;
            int r = idx >> 3, f = (idx & 7) * 4;
            float4 va = *(const float4*)(Ag + (size_t)r * 1024 + kt * 32 + f);
            float4 vah, val;
            split2(va.x, vah.x, val.x); split2(va.y, vah.y, val.y);
            split2(va.z, vah.z, val.z); split2(va.w, vah.w, val.w);
            *(float4*)&Ahi[r][f] = vah;
            *(float4*)&Alo[r][f] = val;
            float4 vb = *(const float4*)(Bg + (size_t)r * 1024 + kt * 32 + f);
            float4 vbh, vbl;
            split2(vb.x, vbh.x, vbl.x); split2(vb.y, vbh.y, vbl.y);
            split2(vb.z, vbh.z, vbl.z); split2(vb.w, vbh.w, vbl.w);
            *(float4*)&Bhi[r][f] = vbh;
            *(float4*)&Blo[r][f] = vbl;
        }
        __syncthreads();
        #pragma unroll
        for (int ks = 0; ks < 4; ks++) {
            const int k0 = ks * 8;
            float ah[4][4], al[4][4], bh[4][2], bl[4][2];
            #pragma unroll
            for (int mf = 0; mf < 4; mf++) {
                int r0 = wm * 64 + mf * 16 + gid;
                ah[mf][0] = Ahi[r0][k0 + tig];       al[mf][0] = Alo[r0][k0 + tig];
                ah[mf][1] = Ahi[r0 + 8][k0 + tig];   al[mf][1] = Alo[r0 + 8][k0 + tig];
                ah[mf][2] = Ahi[r0][k0 + tig + 4];   al[mf][2] = Alo[r0][k0 + tig + 4];
                ah[mf][3] = Ahi[r0 + 8][k0 + tig + 4]; al[mf][3] = Alo[r0 + 8][k0 + tig + 4];
            }
            #pragma unroll
            for (int nf = 0; nf < 4; nf++) {
                int n0 = wn * 32 + nf * 8 + gid;
                bh[nf][0] = Bhi[n0][k0 + tig];     bl[nf][0] = Blo[n0][k0 + tig];
                bh[nf][1] = Bhi[n0][k0 + tig + 4]; bl[nf][1] = Blo[n0][k0 + tig + 4];
            }
            #pragma unroll
            for (int mf = 0; mf < 4; mf++)
                #pragma unroll
                for (int nf = 0; nf < 4; nf++)
                    mma8_3x(c[mf][nf], ah[mf], al[mf],
                            bh[nf][0], bl[nf][0], bh[nf][1], bl[nf][1]);
        }
    }

    // epilogue: thread holds rows (r0, r0+8), cols (gcol, gcol+1) per fragment
    #pragma unroll
    for (int mf = 0; mf < 4; mf++) {
        int r0g = bm * 128 + wm * 64 + mf * 16 + gid;
        int r1g = r0g + 8;
        #pragma unroll
        for (int nf = 0; nf < 4; nf++) {
            int gcol = bn * 128 + wn * 32 + nf * 8 + 2 * tig;
            if (MODE == 0) {
                int which = gcol >> 10, h = (gcol >> 6) & 15, d = gcol & 63;
                float* dst = which == 0 ? g_q : (which == 1 ? g_k : g_v);
                int b0i = r0g >> 11, n0i = r0g & 2047;
                int b1i = r1g >> 11, n1i = r1g & 2047;
                *(float2*)(dst + (((size_t)b0i * H_ + h) * N_ + n0i) * D_ + d) =
                    make_float2(c[mf][nf][0], c[mf][nf][1]);
                *(float2*)(dst + (((size_t)b1i * H_ + h) * N_ + n1i) * D_ + d) =
                    make_float2(c[mf][nf][2], c[mf][nf][3]);
            } else {
                float bx = bias[gcol], by = bias[gcol + 1];
                *(float2*)(out + (size_t)r0g * 1024 + gcol) =
                    make_float2(c[mf][nf][0] + bx, c[mf][nf][1] + by);
                *(float2*)(out + (size_t)r1g * 1024 + gcol) =
                    make_float2(c[mf][nf][2] + bx, c[mf][nf][3] + by);
            }
        }
    }
}

// ================= RMSNorm + RoPE (in place on g_q/g_k) =================
__global__ __launch_bounds__(256) void norm_rope(const float* __restrict__ qn_w,
                                                 const float* __restrict__ kn_w,
                                                 const float* __restrict__ fc,
                                                 const float* __restrict__ fs) {
    int gw = (blockIdx.x * 256 + threadIdx.x) >> 5;
    int lane = threadIdx.x & 31;
    const int half = B_ * H_ * N_;
    float* buf; const float* w; int r;
    if (gw < half) { buf = g_q; w = qn_w; r = gw; }
    else           { buf = g_k; w = kn_w; r = gw - half; }
    int n = r & (N_ - 1);
    float2 v = *(float2*)(buf + (size_t)r * D_ + lane * 2);
    float ss = v.x * v.x + v.y * v.y;
    #pragma unroll
    for (int o = 16; o; o >>= 1) ss += __shfl_xor_sync(0xffffffffu, ss, o);
    float rinv = rsqrtf(ss * (1.0f / D_) + 1e-6f);
    float a = v.x * rinv * w[lane * 2];
    float b = v.y * rinv * w[lane * 2 + 1];
    const float* fcp = fc + n * D_ + lane * 2;
    const float* fsp = fs + n * D_ + lane * 2;
    float c0 = fcp[0], c1 = fcp[1], s0 = fsp[0], s1 = fsp[1];
    *(float2*)(buf + (size_t)r * D_ + lane * 2) = make_float2(a * c0 - b * s0, b * c1 + a * s1);
}

// ================= flash attention: 3xTF32 S, 1xTF32 PV, static softmax =================
// Grid (N/128, B*H). 256 thr, 8 warps; warp w owns q rows [qt*128+16w, +16).
// ||q||=||k||=8 after rmsnorm => |s*scale| <= 8, exp <= e^8: no max tracking needed.
// K pre-split (hi/lo) and V pre-rounded (tf32 rna) by the tile loader.
__global__ __launch_bounds__(256, 1) void flash_attn_mma() {
    extern __shared__ float sm[];
    float* Khi = sm;                      // [64][68]  (key-major, d inner)
    float* Klo = sm + 64 * 68;
    float* Vs  = sm + 2 * 64 * 68;        // [64][68]  tf32-rounded
    const int tid = threadIdx.x;
    const int wid = tid >> 5, lane = tid & 31;
    const int gid = lane >> 2, tig = lane & 3;
    float* Ps = sm + 3 * 64 * 68 + wid * 16 * 68;   // warp-private [16][68]

    const int qt = blockIdx.x, bh = blockIdx.y;
    const int qrow0 = qt * 128 + wid * 16;
    const float SC2 = 0.125f * 1.44269504088896f;   // scale * log2(e)

    // Q fragments hi/lo: cover q rows (gid, gid+8), cols (8ks+tig, +4)
    float aqh[8][4], aql[8][4];
    {
        const float* Qg = g_q + ((size_t)bh * N_ + qrow0) * D_;
        #pragma unroll
        for (int ks = 0; ks < 8; ks++) {
            split2(Qg[(size_t)gid * D_ + ks * 8 + tig],           aqh[ks][0], aql[ks][0]);
            split2(Qg[(size_t)(gid + 8) * D_ + ks * 8 + tig],     aqh[ks][1], aql[ks][1]);
            split2(Qg[(size_t)gid * D_ + ks * 8 + tig + 4],       aqh[ks][2], aql[ks][2]);
            split2(Qg[(size_t)(gid + 8) * D_ + ks * 8 + tig + 4], aqh[ks][3], aql[ks][3]);
        }
    }

    float l0 = 0.f, l1 = 0.f;
    float o[8][4];
    #pragma unroll
    for (int nf = 0; nf < 8; nf++)
        #pragma unroll
        for (int r = 0; r < 4; r++) o[nf][r] = 0.f;

    const float* Kg0 = g_k + (size_t)bh * N_ * D_;
    const float* Vg0 = g_v + (size_t)bh * N_ * D_;

    for (int kt = 0; kt < N_ / 64; kt++) {
        __syncthreads();   // K/V from previous tile fully consumed
        const float* Kg = Kg0 + kt * 64 * D_;
        const float* Vg = Vg0 + kt * 64 * D_;
        #pragma unroll
        for (int it = 0; it < 4; it++) {
            int idx = tid + it * 256;            // 0..1023
            int r = idx >> 4, f = (idx & 15) * 4;
            float4 kv = *(const float4*)(Kg + (size_t)r * D_ + f);
            float4 kh, kl;
            split2(kv.x, kh.x, kl.x); split2(kv.y, kh.y, kl.y);
            split2(kv.z, kh.z, kl.z); split2(kv.w, kh.w, kl.w);
            *(float4*)(Khi + r * 68 + f) = kh;
            *(float4*)(Klo + r * 68 + f) = kl;
            float4 vv = *(const float4*)(Vg + (size_t)r * D_ + f);
            vv.x = tf32r(vv.x); vv.y = tf32r(vv.y);
            vv.z = tf32r(vv.z); vv.w = tf32r(vv.w);
            *(float4*)(Vs + r * 68 + f) = vv;
        }
        __syncthreads();

        // S = Q @ K^T (3xTF32): B-frag = K[n=8nf+gid][k=8ks+tig]  (conflict-free)
        float s[8][4];
        #pragma unroll
        for (int nf = 0; nf < 8; nf++) {
            s[nf][0] = s[nf][1] = s[nf][2] = s[nf][3] = 0.f;
            const float* kbh = Khi + (nf * 8 + gid) * 68;
            const float* kbl = Klo + (nf * 8 + gid) * 68;
            #pragma unroll
            for (int ks = 0; ks < 8; ks++)
                mma8_3x(s[nf], aqh[ks], aql[ks],
                        kbh[ks * 8 + tig], kbl[ks * 8 + tig],
                        kbh[ks * 8 + tig + 4], kbl[ks * 8 + tig + 4]);
        }

        // static softmax: p = exp2(s*SC2), no max subtraction (bounded by e^8)
        float sum0 = 0.f, sum1 = 0.f;
        #pragma unroll
        for (int nf = 0; nf < 8; nf++) {
            float p0 = exp2a(s[nf][0] * SC2);
            float p1 = exp2a(s[nf][1] * SC2);
            float p2 = exp2a(s[nf][2] * SC2);
            float p3 = exp2a(s[nf][3] * SC2);
            sum0 += p0 + p1; sum1 += p2 + p3;
            int cc = nf * 8 + 2 * tig;
            *(float2*)(Ps + gid * 68 + cc)       = make_float2(tf32r(p0), tf32r(p1));
            *(float2*)(Ps + (gid + 8) * 68 + cc) = make_float2(tf32r(p2), tf32r(p3));
        }
        sum0 += __shfl_xor_sync(0xffffffffu, sum0, 1);
        sum0 += __shfl_xor_sync(0xffffffffu, sum0, 2);
        sum1 += __shfl_xor_sync(0xffffffffu, sum1, 1);
        sum1 += __shfl_xor_sync(0xffffffffu, sum1, 2);
        l0 += sum0;
        l1 += sum1;
        __syncwarp();

        // O += P @ V (1xTF32): A-frag from warp-private Ps, B-frag = Vs[k][n]
        #pragma unroll
        for (int ks = 0; ks < 8; ks++) {
            float ap[4];
            ap[0] = Ps[gid * 68 + ks * 8 + tig];
            ap[1] = Ps[(gid + 8) * 68 + ks * 8 + tig];
            ap[2] = Ps[gid * 68 + ks * 8 + tig + 4];
            ap[3] = Ps[(gid + 8) * 68 + ks * 8 + tig + 4];
            #pragma unroll
            for (int nf = 0; nf < 8; nf++) {
                float b0 = Vs[(ks * 8 + tig) * 68 + nf * 8 + gid];
                float b1 = Vs[(ks * 8 + tig + 4) * 68 + nf * 8 + gid];
                mma8(o[nf], ap, b0, b1);
            }
        }
        __syncwarp();   // Ps reads done before next tile's stores
    }

    // epilogue: write [B,N,C]
    float inv0 = 1.f / l0, inv1 = 1.f / l1;
    const int b = bh >> 4, h = bh & 15;
    float* Og = g_o + ((size_t)b * N_ + qrow0) * C_ + h * D_;
    #pragma unroll
    for (int nf = 0; nf < 8; nf++) {
        int cc = nf * 8 + 2 * tig;
        *(float2*)(Og + (size_t)gid * C_ + cc) =
            make_float2(o[nf][0] * inv0, o[nf][1] * inv0);
        *(float2*)(Og + (size_t)(gid + 8) * C_ + cc) =
            make_float2(o[nf][2] * inv1, o[nf][3] * inv1);
    }
}

// ================= launch =================
extern "C" void kernel_launch(void* const* d_in, const int* in_sizes, int n_in,
                              void* d_out, int out_size) {
    const float* x      = (const float*)d_in[0];
    const float* w_qkv  = (const float*)d_in[1];
    const float* w_proj = (const float*)d_in[2];
    const float* b_proj = (const float*)d_in[3];
    const float* qn_w   = (const float*)d_in[4];
    const float* kn_w   = (const float*)d_in[5];
    const float* fc     = (const float*)d_in[6];
    const float* fs     = (const float*)d_in[7];
    float* out = (float*)d_out;

    float* wqkvT;  cudaGetSymbolAddress((void**)&wqkvT,  g_wqkvT);
    float* wprojT; cudaGetSymbolAddress((void**)&wprojT, g_wprojT);
    float* oPtr;   cudaGetSymbolAddress((void**)&oPtr,   g_o);

    transpose_w<<<dim3(3072 / 32, 1024 / 32), dim3(32, 8)>>>(w_qkv, wqkvT, 1024, 3072);
    transpose_w<<<dim3(1024 / 32, 1024 / 32), dim3(32, 8)>>>(w_proj, wprojT, 1024, 1024);

    const int gemm_smem = 4 * 128 * 36 * 4;   // 73728 B
    cudaFuncSetAttribute(gemm_mma<0>, cudaFuncAttributeMaxDynamicSharedMemorySize, gemm_smem);
    cudaFuncSetAttribute(gemm_mma<1>, cudaFuncAttributeMaxDynamicSharedMemorySize, gemm_smem);

    gemm_mma<0><<<dim3(24, 64), 256, gemm_smem>>>(x, wqkvT, nullptr, nullptr);
    norm_rope<<<32768, 256>>>(qn_w, kn_w, fc, fs);

    const int attn_smem = (3 * 64 * 68 + 8 * 16 * 68) * 4;   // 87040 B
    cudaFuncSetAttribute(flash_attn_mma, cudaFuncAttributeMaxDynamicSharedMemorySize, attn_smem);
    flash_attn_mma<<<dim3(16, 64), 256, attn_smem>>>();

    gemm_mma<1><<<dim3(8, 64), 256, gemm_smem>>>(oPtr, wprojT, b_proj, out);
}

// round 9
// speedup vs baseline: 2.4656x; 1.4796x over previous
#include <cuda_runtime.h>
#include <cstdint>

#define B_ 4
#define N_ 2048
#define C_ 1024
#define H_ 16
#define D_ 64
#define QKV_ELEMS (B_*H_*N_*D_)   // 8388608

// Scratch (allocation-free rule: __device__ globals)
__device__ float g_q[QKV_ELEMS];
__device__ float g_k[QKV_ELEMS];
__device__ float g_v[QKV_ELEMS];
__device__ float g_o[QKV_ELEMS];          // attention out, [B,N,C] layout
__device__ float g_wqkvT[3072 * 1024];    // w_qkv^T  [3072,1024], rna-tf32 pre-rounded
__device__ float g_wprojT[1024 * 1024];   // w_proj^T [1024,1024], rna-tf32 pre-rounded

// ---------------- helpers ----------------
__device__ __forceinline__ float tf32r(float x) {
    uint32_t u;
    asm("cvt.rna.tf32.f32 %0, %1;" : "=r"(u) : "f"(x));
    return __uint_as_float(u);
}
__device__ __forceinline__ void split2(float x, float& hi, float& lo) {
    hi = tf32r(x);
    lo = tf32r(x - hi);
}
__device__ __forceinline__ float exp2a(float x) {
    float r; asm("ex2.approx.f32 %0, %1;" : "=f"(r) : "f"(x)); return r;
}
__device__ __forceinline__ uint32_t smem_u32(const void* p) {
    uint32_t a;
    asm("{ .reg .u64 t; cvta.to.shared.u64 t, %1; cvt.u32.u64 %0, t; }" : "=r"(a) : "l"(p));
    return a;
}
__device__ __forceinline__ void cp16(uint32_t dst, const void* src) {
    asm volatile("cp.async.cg.shared.global [%0], [%1], 16;" :: "r"(dst), "l"(src));
}
#define CP_COMMIT() asm volatile("cp.async.commit_group;" ::: "memory")
#define CP_WAIT(n)  asm volatile("cp.async.wait_group %0;" :: "n"(n) : "memory")

// m16n8k8 tf32 mma: D += A*B. A: 4 regs, B: 2 regs, C/D: 4 f32.
// B operands must be rna-pre-rounded tf32 values (HW truncation is then exact).
__device__ __forceinline__ void mma8(float* d, const float* a, float b0, float b1) {
    asm volatile(
        "mma.sync.aligned.m16n8k8.row.col.f32.tf32.tf32.f32 "
        "{%0,%1,%2,%3}, {%4,%5,%6,%7}, {%8,%9}, {%0,%1,%2,%3};"
        : "+f"(d[0]), "+f"(d[1]), "+f"(d[2]), "+f"(d[3])
        : "r"(__float_as_uint(a[0])), "r"(__float_as_uint(a[1])),
          "r"(__float_as_uint(a[2])), "r"(__float_as_uint(a[3])),
          "r"(__float_as_uint(b0)),  "r"(__float_as_uint(b1)));
}
// 2xTF32: d += (ahi + alo) * b  — A split (near-exact), B exact tf32
__device__ __forceinline__ void mma8_2x(float* d, const float* ahi, const float* alo,
                                        float b0, float b1) {
    mma8(d, alo, b0, b1);
    mma8(d, ahi, b0, b1);
}

// ================= weight transpose (once): dst[c][r] = rna_tf32(src[r][c]) =================
__global__ __launch_bounds__(256) void transpose_w(const float* __restrict__ src,
                                                   float* __restrict__ dst,
                                                   int R, int Ccols) {
    __shared__ float t[32][33];
    int bx = blockIdx.x * 32, by = blockIdx.y * 32;
    int tx = threadIdx.x, ty = threadIdx.y;      // 32 x 8
    #pragma unroll
    for (int i = 0; i < 32; i += 8)
        t[ty + i][tx] = tf32r(src[(size_t)(by + ty + i) * Ccols + bx + tx]);
    __syncthreads();
    #pragma unroll
    for (int i = 0; i < 32; i += 8)
        dst[(size_t)(bx + ty + i) * R + by + tx] = t[tx][ty + i];
}

// ================= 2xTF32 mma.sync GEMM, cp.async double-buffered =================
// C[M,NN] = A[M,1024] @ BT[NN,1024]^T ; BM=BN=128, BK=32; 8 warps, 64x32 warp tiles.
// Raw A tiles in smem (split at fragment load); B pre-rounded rna-tf32 in global.
// MODE 0: qkv (scatter into g_q/g_k/g_v [B,H,N,D]; v rna-rounded) ; MODE 1: proj (bias + out)
template<int MODE>
__global__ __launch_bounds__(256, 2) void gemm_mma(const float* __restrict__ A,
                                                   const float* __restrict__ BT,
                                                   const float* __restrict__ bias,
                                                   float* __restrict__ out) {
    extern __shared__ float gsm[];
    float (*As)[128][36] = (float(*)[128][36])gsm;             // [2][128][36]
    float (*Bs)[128][36] = (float(*)[128][36])(gsm + 2 * 128 * 36);
    const uint32_t sA = smem_u32(gsm);
    const uint32_t sB = smem_u32(gsm + 2 * 128 * 36);
    const int tid = threadIdx.x;
    const int wid = tid >> 5, lane = tid & 31;
    const int gid = lane >> 2, tig = lane & 3;
    const int wm = wid & 1, wn = wid >> 1;       // 2 x 4 warp grid
    const int bn = blockIdx.x, bm = blockIdx.y;

    float c[4][4][4];
    #pragma unroll
    for (int mf = 0; mf < 4; mf++)
        #pragma unroll
        for (int nf = 0; nf < 4; nf++)
            #pragma unroll
            for (int r = 0; r < 4; r++) c[mf][nf][r] = 0.f;

    const float* Ag = A + (size_t)(bm * 128) * 1024;
    const float* Bg = BT + (size_t)(bn * 128) * 1024;
    const int lr = tid >> 3, lf = (tid & 7) * 4;   // loader row/col base

    auto issue = [&](int t) {
        const int buf = t & 1;
        #pragma unroll
        for (int it = 0; it < 4; it++) {
            int r = lr + it * 32;
            cp16(sA + (((buf * 128 + r) * 36 + lf) << 2), Ag + (size_t)r * 1024 + t * 32 + lf);
            cp16(sB + (((buf * 128 + r) * 36 + lf) << 2), Bg + (size_t)r * 1024 + t * 32 + lf);
        }
        CP_COMMIT();
    };

    issue(0);
    for (int t = 0; t < 32; t++) {
        if (t < 31) { issue(t + 1); CP_WAIT(1); }
        else        { CP_WAIT(0); }
        __syncthreads();
        const int cb = t & 1;
        #pragma unroll
        for (int ks = 0; ks < 4; ks++) {
            const int k0 = ks * 8;
            float ah[4][4], al[4][4], b[4][2];
            #pragma unroll
            for (int mf = 0; mf < 4; mf++) {
                int r0 = wm * 64 + mf * 16 + gid;
                split2(As[cb][r0][k0 + tig],         ah[mf][0], al[mf][0]);
                split2(As[cb][r0 + 8][k0 + tig],     ah[mf][1], al[mf][1]);
                split2(As[cb][r0][k0 + tig + 4],     ah[mf][2], al[mf][2]);
                split2(As[cb][r0 + 8][k0 + tig + 4], ah[mf][3], al[mf][3]);
            }
            #pragma unroll
            for (int nf = 0; nf < 4; nf++) {
                int n0 = wn * 32 + nf * 8 + gid;
                b[nf][0] = Bs[cb][n0][k0 + tig];
                b[nf][1] = Bs[cb][n0][k0 + tig + 4];
            }
            #pragma unroll
            for (int mf = 0; mf < 4; mf++)
                #pragma unroll
                for (int nf = 0; nf < 4; nf++)
                    mma8_2x(c[mf][nf], ah[mf], al[mf], b[nf][0], b[nf][1]);
        }
        __syncthreads();
    }

    // epilogue: thread holds rows (r0, r0+8), cols (gcol, gcol+1) per fragment
    #pragma unroll
    for (int mf = 0; mf < 4; mf++) {
        int r0g = bm * 128 + wm * 64 + mf * 16 + gid;
        int r1g = r0g + 8;
        #pragma unroll
        for (int nf = 0; nf < 4; nf++) {
            int gcol = bn * 128 + wn * 32 + nf * 8 + 2 * tig;
            if (MODE == 0) {
                int which = gcol >> 10, h = (gcol >> 6) & 15, d = gcol & 63;
                float* dst = which == 0 ? g_q : (which == 1 ? g_k : g_v);
                int b0i = r0g >> 11, n0i = r0g & 2047;
                int b1i = r1g >> 11, n1i = r1g & 2047;
                float2 v0 = make_float2(c[mf][nf][0], c[mf][nf][1]);
                float2 v1 = make_float2(c[mf][nf][2], c[mf][nf][3]);
                if (which == 2) {   // V feeds PV as raw B operand: pre-round rna
                    v0.x = tf32r(v0.x); v0.y = tf32r(v0.y);
                    v1.x = tf32r(v1.x); v1.y = tf32r(v1.y);
                }
                *(float2*)(dst + (((size_t)b0i * H_ + h) * N_ + n0i) * D_ + d) = v0;
                *(float2*)(dst + (((size_t)b1i * H_ + h) * N_ + n1i) * D_ + d) = v1;
            } else {
                float bx = bias[gcol], by = bias[gcol + 1];
                *(float2*)(out + (size_t)r0g * 1024 + gcol) =
                    make_float2(c[mf][nf][0] + bx, c[mf][nf][1] + by);
                *(float2*)(out + (size_t)r1g * 1024 + gcol) =
                    make_float2(c[mf][nf][2] + bx, c[mf][nf][3] + by);
            }
        }
    }
}

// ================= RMSNorm + RoPE (in place on g_q/g_k; k rna-rounded) =================
__global__ __launch_bounds__(256) void norm_rope(const float* __restrict__ qn_w,
                                                 const float* __restrict__ kn_w,
                                                 const float* __restrict__ fc,
                                                 const float* __restrict__ fs) {
    int gw = (blockIdx.x * 256 + threadIdx.x) >> 5;
    int lane = threadIdx.x & 31;
    const int half = B_ * H_ * N_;
    float* buf; const float* w; int r; bool isk;
    if (gw < half) { buf = g_q; w = qn_w; r = gw; isk = false; }
    else           { buf = g_k; w = kn_w; r = gw - half; isk = true; }
    int n = r & (N_ - 1);
    float2 v = *(float2*)(buf + (size_t)r * D_ + lane * 2);
    float ss = v.x * v.x + v.y * v.y;
    #pragma unroll
    for (int o = 16; o; o >>= 1) ss += __shfl_xor_sync(0xffffffffu, ss, o);
    float rinv = rsqrtf(ss * (1.0f / D_) + 1e-6f);
    float a = v.x * rinv * w[lane * 2];
    float b = v.y * rinv * w[lane * 2 + 1];
    const float* fcp = fc + n * D_ + lane * 2;
    const float* fsp = fs + n * D_ + lane * 2;
    float c0 = fcp[0], c1 = fcp[1], s0 = fsp[0], s1 = fsp[1];
    float o0 = a * c0 - b * s0, o1 = b * c1 + a * s1;
    if (isk) { o0 = tf32r(o0); o1 = tf32r(o1); }   // K feeds S as raw B operand
    *(float2*)(buf + (size_t)r * D_ + lane * 2) = make_float2(o0, o1);
}

// ================= flash attention: 2xTF32 S, 1xTF32 PV, cp.async pipeline =================
// Grid (N/128, B*H). 256 thr, 8 warps; warp w owns q rows [qt*128+16w, +16).
// ||q||=||k||=8 after rmsnorm => |s*scale| <= 8: static softmax, no max tracking.
// K (rna-pre-rounded) stride 68; V (rna-pre-rounded) stride 72 (conflict-free PV B-frags).
// P rna-rounded at store. All mma operands are exact tf32 or hi/lo split.
__global__ __launch_bounds__(256, 1) void flash_attn_mma() {
    extern __shared__ float sm[];
    float* Ks = sm;                        // [2][64][68]
    float* Vs = sm + 2 * 64 * 68;          // [2][64][72]
    float* PsBase = sm + 2 * 64 * 68 + 2 * 64 * 72;   // [8][16][68]
    const uint32_t sK = smem_u32(Ks);
    const uint32_t sV = smem_u32(Vs);
    const int tid = threadIdx.x;
    const int wid = tid >> 5, lane = tid & 31;
    const int gid = lane >> 2, tig = lane & 3;
    float* Ps = PsBase + wid * 16 * 68;    // warp-private

    const int qt = blockIdx.x, bh = blockIdx.y;
    const int qrow0 = qt * 128 + wid * 16;
    const float SC2 = 0.125f * 1.44269504088896f;   // scale * log2(e)

    // Q fragments hi/lo: cover q rows (gid, gid+8), cols (8ks+tig, +4)
    float aqh[8][4], aql[8][4];
    {
        const float* Qg = g_q + ((size_t)bh * N_ + qrow0) * D_;
        #pragma unroll
        for (int ks = 0; ks < 8; ks++) {
            split2(Qg[(size_t)gid * D_ + ks * 8 + tig],           aqh[ks][0], aql[ks][0]);
            split2(Qg[(size_t)(gid + 8) * D_ + ks * 8 + tig],     aqh[ks][1], aql[ks][1]);
            split2(Qg[(size_t)gid * D_ + ks * 8 + tig + 4],       aqh[ks][2], aql[ks][2]);
            split2(Qg[(size_t)(gid + 8) * D_ + ks * 8 + tig + 4], aqh[ks][3], aql[ks][3]);
        }
    }

    float l0 = 0.f, l1 = 0.f;
    float o[8][4];
    #pragma unroll
    for (int nf = 0; nf < 8; nf++)
        #pragma unroll
        for (int r = 0; r < 4; r++) o[nf][r] = 0.f;

    const float* Kg0 = g_k + (size_t)bh * N_ * D_;
    const float* Vg0 = g_v + (size_t)bh * N_ * D_;
    const int lr = tid >> 4, lf = (tid & 15) * 4;   // loader row/col base

    auto issueKV = [&](int t) {
        const int buf = t & 1;
        const float* Kg = Kg0 + t * 64 * D_;
        const float* Vg = Vg0 + t * 64 * D_;
        #pragma unroll
        for (int it = 0; it < 4; it++) {
            int r = lr + it * 16;
            cp16(sK + (((buf * 64 + r) * 68 + lf) << 2), Kg + (size_t)r * D_ + lf);
            cp16(sV + (((buf * 64 + r) * 72 + lf) << 2), Vg + (size_t)r * D_ + lf);
        }
        CP_COMMIT();
    };

    issueKV(0);
    for (int kt = 0; kt < N_ / 64; kt++) {
        if (kt < 31) { issueKV(kt + 1); CP_WAIT(1); }
        else         { CP_WAIT(0); }
        __syncthreads();
        const float* Kc = Ks + (kt & 1) * 64 * 68;
        const float* Vc = Vs + (kt & 1) * 64 * 72;

        // S = Q @ K^T (2xTF32): B-frag = K[n=8nf+gid][k=8ks+tig]  (conflict-free)
        float s[8][4];
        #pragma unroll
        for (int nf = 0; nf < 8; nf++) {
            s[nf][0] = s[nf][1] = s[nf][2] = s[nf][3] = 0.f;
            const float* kb = Kc + (nf * 8 + gid) * 68;
            #pragma unroll
            for (int ks = 0; ks < 8; ks++)
                mma8_2x(s[nf], aqh[ks], aql[ks],
                        kb[ks * 8 + tig], kb[ks * 8 + tig + 4]);
        }

        // static softmax: p = exp2(s*SC2), no max subtraction (bounded by e^8)
        float sum0 = 0.f, sum1 = 0.f;
        #pragma unroll
        for (int nf = 0; nf < 8; nf++) {
            float p0 = exp2a(s[nf][0] * SC2);
            float p1 = exp2a(s[nf][1] * SC2);
            float p2 = exp2a(s[nf][2] * SC2);
            float p3 = exp2a(s[nf][3] * SC2);
            sum0 += p0 + p1; sum1 += p2 + p3;
            int cc = nf * 8 + 2 * tig;
            *(float2*)(Ps + gid * 68 + cc)       = make_float2(tf32r(p0), tf32r(p1));
            *(float2*)(Ps + (gid + 8) * 68 + cc) = make_float2(tf32r(p2), tf32r(p3));
        }
        sum0 += __shfl_xor_sync(0xffffffffu, sum0, 1);
        sum0 += __shfl_xor_sync(0xffffffffu, sum0, 2);
        sum1 += __shfl_xor_sync(0xffffffffu, sum1, 1);
        sum1 += __shfl_xor_sync(0xffffffffu, sum1, 2);
        l0 += sum0;
        l1 += sum1;
        __syncwarp();

        // O += P @ V (1xTF32): A-frag from warp-private Ps, B-frag = V[k][n]
        #pragma unroll
        for (int ks = 0; ks < 8; ks++) {
            float ap[4];
            ap[0] = Ps[gid * 68 + ks * 8 + tig];
            ap[1] = Ps[(gid + 8) * 68 + ks * 8 + tig];
            ap[2] = Ps[gid * 68 + ks * 8 + tig + 4];
            ap[3] = Ps[(gid + 8) * 68 + ks * 8 + tig + 4];
            #pragma unroll
            for (int nf = 0; nf < 8; nf++) {
                float b0 = Vc[(ks * 8 + tig) * 72 + nf * 8 + gid];
                float b1 = Vc[(ks * 8 + tig + 4) * 72 + nf * 8 + gid];
                mma8(o[nf], ap, b0, b1);
            }
        }
        __syncthreads();   // tile fully consumed before its buffer is refilled
    }

    // epilogue: write [B,N,C]
    float inv0 = 1.f / l0, inv1 = 1.f / l1;
    const int b = bh >> 4, h = bh & 15;
    float* Og = g_o + ((size_t)b * N_ + qrow0) * C_ + h * D_;
    #pragma unroll
    for (int nf = 0; nf < 8; nf++) {
        int cc = nf * 8 + 2 * tig;
        *(float2*)(Og + (size_t)gid * C_ + cc) =
            make_float2(o[nf][0] * inv0, o[nf][1] * inv0);
        *(float2*)(Og + (size_t)(gid + 8) * C_ + cc) =
            make_float2(o[nf][2] * inv1, o[nf][3] * inv1);
    }
}

// ================= launch =================
extern "C" void kernel_launch(void* const* d_in, const int* in_sizes, int n_in,
                              void* d_out, int out_size) {
    const float* x      = (const float*)d_in[0];
    const float* w_qkv  = (const float*)d_in[1];
    const float* w_proj = (const float*)d_in[2];
    const float* b_proj = (const float*)d_in[3];
    const float* qn_w   = (const float*)d_in[4];
    const float* kn_w   = (const float*)d_in[5];
    const float* fc     = (const float*)d_in[6];
    const float* fs     = (const float*)d_in[7];
    float* out = (float*)d_out;

    float* wqkvT;  cudaGetSymbolAddress((void**)&wqkvT,  g_wqkvT);
    float* wprojT; cudaGetSymbolAddress((void**)&wprojT, g_wprojT);
    float* oPtr;   cudaGetSymbolAddress((void**)&oPtr,   g_o);

    transpose_w<<<dim3(3072 / 32, 1024 / 32), dim3(32, 8)>>>(w_qkv, wqkvT, 1024, 3072);
    transpose_w<<<dim3(1024 / 32, 1024 / 32), dim3(32, 8)>>>(w_proj, wprojT, 1024, 1024);

    const int gemm_smem = 4 * 128 * 36 * 4;   // 73728 B (2 raw A bufs + 2 B bufs)
    cudaFuncSetAttribute(gemm_mma<0>, cudaFuncAttributeMaxDynamicSharedMemorySize, gemm_smem);
    cudaFuncSetAttribute(gemm_mma<1>, cudaFuncAttributeMaxDynamicSharedMemorySize, gemm_smem);

    gemm_mma<0><<<dim3(24, 64), 256, gemm_smem>>>(x, wqkvT, nullptr, nullptr);
    norm_rope<<<32768, 256>>>(qn_w, kn_w, fc, fs);

    const int attn_smem = (2 * 64 * 68 + 2 * 64 * 72 + 8 * 16 * 68) * 4;   // 106496 B
    cudaFuncSetAttribute(flash_attn_mma, cudaFuncAttributeMaxDynamicSharedMemorySize, attn_smem);
    flash_attn_mma<<<dim3(16, 64), 256, attn_smem>>>();

    gemm_mma<1><<<dim3(8, 64), 256, gemm_smem>>>(oPtr, wprojT, b_proj, out);
}

// round 10
// speedup vs baseline: 4.1696x; 1.6911x over previous
#include <cuda_runtime.h>
#include <cuda_fp16.h>
#include <cstdint>

#define B_ 4
#define N_ 2048
#define C_ 1024
#define H_ 16
#define D_ 64
#define QKV_ELEMS (B_*H_*N_*D_)   // 8388608 == 8192*1024

// Scratch (allocation-free rule: __device__ globals)
__device__ float  g_q[QKV_ELEMS];          // qkv out, pre-norm fp32 [B,H,N,D]
__device__ float  g_k[QKV_ELEMS];
__device__ __half g_qh[QKV_ELEMS];         // post-norm Q hi/lo [B,H,N,D]
__device__ __half g_ql[QKV_ELEMS];
__device__ __half g_k16[QKV_ELEMS];        // post-norm K, rna fp16
__device__ __half g_vt16[QKV_ELEMS];       // V transposed [B,H,D,N], rna fp16
__device__ __half g_oh[QKV_ELEMS];         // attn out hi/lo [B,N,C]
__device__ __half g_ol[QKV_ELEMS];
__device__ __half g_xh[QKV_ELEMS];         // x split hi/lo [B*N, C]
__device__ __half g_xl[QKV_ELEMS];
__device__ __half g_wqkvT16[3072 * 1024];  // w_qkv^T rna fp16
__device__ __half g_wprojT16[1024 * 1024]; // w_proj^T rna fp16

// ---------------- helpers ----------------
__device__ __forceinline__ uint32_t pkh2(float lo, float hi) {
    uint32_t r; asm("cvt.rn.f16x2.f32 %0, %1, %2;" : "=r"(r) : "f"(hi), "f"(lo)); return r;
}
__device__ __forceinline__ float2 uph2(uint32_t v) {
    float2 r;
    asm("{.reg .f16 l, h;\n\t mov.b32 {l, h}, %2;\n\t cvt.f32.f16 %0, l;\n\t cvt.f32.f16 %1, h;}"
        : "=f"(r.x), "=f"(r.y) : "r"(v));
    return r;
}
// split pair (a0,a1) into packed fp16 hi and packed fp16 residual-lo
__device__ __forceinline__ void splith2(float a0, float a1, uint32_t& h, uint32_t& l) {
    h = pkh2(a0, a1);
    float2 hf = uph2(h);
    l = pkh2(a0 - hf.x, a1 - hf.y);
}
__device__ __forceinline__ float exp2a(float x) {
    float r; asm("ex2.approx.f32 %0, %1;" : "=f"(r) : "f"(x)); return r;
}
__device__ __forceinline__ uint32_t smem_u32(const void* p) {
    uint32_t a;
    asm("{ .reg .u64 t; cvta.to.shared.u64 t, %1; cvt.u32.u64 %0, t; }" : "=r"(a) : "l"(p));
    return a;
}
__device__ __forceinline__ void cp16(uint32_t dst, const void* src) {
    asm volatile("cp.async.cg.shared.global [%0], [%1], 16;" :: "r"(dst), "l"(src));
}
#define CP_COMMIT() asm volatile("cp.async.commit_group;" ::: "memory")
#define CP_WAIT(n)  asm volatile("cp.async.wait_group %0;" :: "n"(n) : "memory")

// m16n8k16 fp16 mma, fp32 accum: D += A*B. A: 4 b32 (f16x2), B: 2 b32, C/D: 4 f32.
__device__ __forceinline__ void mma16(float* d, const uint32_t* a, uint32_t b0, uint32_t b1) {
    asm volatile(
        "mma.sync.aligned.m16n8k16.row.col.f32.f16.f16.f32 "
        "{%0,%1,%2,%3}, {%4,%5,%6,%7}, {%8,%9}, {%0,%1,%2,%3};"
        : "+f"(d[0]), "+f"(d[1]), "+f"(d[2]), "+f"(d[3])
        : "r"(a[0]), "r"(a[1]), "r"(a[2]), "r"(a[3]), "r"(b0), "r"(b1));
}

// ================= prep: split x into fp16 hi/lo =================
__global__ __launch_bounds__(256) void split_x(const float* __restrict__ x) {
    int i = blockIdx.x * 256 + threadIdx.x;     // pair index, 4.2M total
    float2 v = *(const float2*)(x + (size_t)i * 2);
    uint32_t h, l; splith2(v.x, v.y, h, l);
    ((uint32_t*)g_xh)[i] = h;
    ((uint32_t*)g_xl)[i] = l;
}

// ================= weight transpose: dst[c][r] = rna_fp16(src[r][c]) =================
__global__ __launch_bounds__(256) void transpose_w16(const float* __restrict__ src,
                                                     __half* __restrict__ dst,
                                                     int R, int Ccols) {
    __shared__ float t[32][33];
    int bx = blockIdx.x * 32, by = blockIdx.y * 32;
    int tx = threadIdx.x, ty = threadIdx.y;      // 32 x 8
    #pragma unroll
    for (int i = 0; i < 32; i += 8)
        t[ty + i][tx] = src[(size_t)(by + ty + i) * Ccols + bx + tx];
    __syncthreads();
    #pragma unroll
    for (int i = 0; i < 32; i += 8)
        dst[(size_t)(bx + ty + i) * R + by + tx] = __float2half_rn(t[tx][ty + i]);
}

// ================= fp16 2-term mma GEMM, cp.async double-buffered =================
// C[M,NN] = (Ah+Al)[M,1024] @ Bh[NN,1024]^T ; BM=BN=128, BK=32 (2 k16 slabs).
// MODE 0: qkv (q,k fp32 scatter; v -> g_vt16 transposed) ; MODE 1: proj (bias + out)
template<int MODE>
__global__ __launch_bounds__(256, 2) void gemm_f16(const __half* __restrict__ Agh,
                                                   const __half* __restrict__ Agl,
                                                   const __half* __restrict__ Bgh,
                                                   const float* __restrict__ bias,
                                                   float* __restrict__ out) {
    extern __shared__ __half gsm[];
    __half* Ahs = gsm;                      // [2][128][40]
    __half* Als = gsm + 2 * 128 * 40;
    __half* Bhs = gsm + 4 * 128 * 40;
    const uint32_t sAh = smem_u32(Ahs), sAl = smem_u32(Als), sBh = smem_u32(Bhs);
    const int tid = threadIdx.x;
    const int wid = tid >> 5, lane = tid & 31;
    const int gid = lane >> 2, tig = lane & 3;
    const int wm = wid & 1, wn = wid >> 1;       // 2 x 4 warp grid
    const int bn = blockIdx.x, bm = blockIdx.y;

    float c[4][4][4];
    #pragma unroll
    for (int mf = 0; mf < 4; mf++)
        #pragma unroll
        for (int nf = 0; nf < 4; nf++)
            #pragma unroll
            for (int r = 0; r < 4; r++) c[mf][nf][r] = 0.f;

    const __half* Ah0 = Agh + (size_t)(bm * 128) * 1024;
    const __half* Al0 = Agl + (size_t)(bm * 128) * 1024;
    const __half* Bh0 = Bgh + (size_t)(bn * 128) * 1024;
    const int lr = tid >> 2, lc = (tid & 3) * 8;   // loader: 64 row-pairs, 8-half chunks

    auto issue = [&](int t) {
        const int buf = t & 1;
        #pragma unroll
        for (int it = 0; it < 2; it++) {
            int r = lr + it * 64;
            uint32_t so = ((buf * 128 + r) * 40 + lc) * 2;
            size_t go = (size_t)r * 1024 + t * 32 + lc;
            cp16(sAh + so, Ah0 + go);
            cp16(sAl + so, Al0 + go);
            cp16(sBh + so, Bh0 + go);
        }
        CP_COMMIT();
    };

    issue(0);
    for (int t = 0; t < 32; t++) {
        if (t < 31) { issue(t + 1); CP_WAIT(1); }
        else        { CP_WAIT(0); }
        __syncthreads();
        const __half* Ab = Ahs + (t & 1) * (128 * 40);
        const __half* Lb = Als + (t & 1) * (128 * 40);
        const __half* Bb = Bhs + (t & 1) * (128 * 40);
        #pragma unroll
        for (int ks = 0; ks < 2; ks++) {
            uint32_t bh[4][2];
            #pragma unroll
            for (int nf = 0; nf < 4; nf++) {
                const __half* bp = Bb + (wn * 32 + nf * 8 + gid) * 40 + ks * 16 + 2 * tig;
                bh[nf][0] = *(const uint32_t*)bp;
                bh[nf][1] = *(const uint32_t*)(bp + 8);
            }
            #pragma unroll
            for (int mf = 0; mf < 4; mf++) {
                const __half* ap = Ab + (wm * 64 + mf * 16 + gid) * 40 + ks * 16 + 2 * tig;
                const __half* lp = Lb + (wm * 64 + mf * 16 + gid) * 40 + ks * 16 + 2 * tig;
                uint32_t ah[4] = { *(const uint32_t*)ap, *(const uint32_t*)(ap + 8 * 40),
                                   *(const uint32_t*)(ap + 8), *(const uint32_t*)(ap + 8 * 40 + 8) };
                uint32_t al[4] = { *(const uint32_t*)lp, *(const uint32_t*)(lp + 8 * 40),
                                   *(const uint32_t*)(lp + 8), *(const uint32_t*)(lp + 8 * 40 + 8) };
                #pragma unroll
                for (int nf = 0; nf < 4; nf++) {
                    mma16(c[mf][nf], al, bh[nf][0], bh[nf][1]);
                    mma16(c[mf][nf], ah, bh[nf][0], bh[nf][1]);
                }
            }
        }
        __syncthreads();
    }

    // epilogue: thread holds rows (r0, r0+8), cols (gcol, gcol+1) per fragment
    #pragma unroll
    for (int mf = 0; mf < 4; mf++) {
        int r0g = bm * 128 + wm * 64 + mf * 16 + gid;
        int r1g = r0g + 8;
        #pragma unroll
        for (int nf = 0; nf < 4; nf++) {
            int gcol = bn * 128 + wn * 32 + nf * 8 + 2 * tig;
            if (MODE == 0) {
                int which = gcol >> 10, h = (gcol >> 6) & 15, d = gcol & 63;
                int b0i = r0g >> 11, n0i = r0g & 2047;
                int b1i = r1g >> 11, n1i = r1g & 2047;
                if (which == 2) {    // v: rna fp16, transposed [B,H,D,N]
                    size_t vb0 = ((size_t)(b0i * H_ + h)) * 64;
                    size_t vb1 = ((size_t)(b1i * H_ + h)) * 64;
                    g_vt16[(vb0 + d) * 2048 + n0i]     = __float2half_rn(c[mf][nf][0]);
                    g_vt16[(vb0 + d + 1) * 2048 + n0i] = __float2half_rn(c[mf][nf][1]);
                    g_vt16[(vb1 + d) * 2048 + n1i]     = __float2half_rn(c[mf][nf][2]);
                    g_vt16[(vb1 + d + 1) * 2048 + n1i] = __float2half_rn(c[mf][nf][3]);
                } else {
                    float* dst = which == 0 ? g_q : g_k;
                    *(float2*)(dst + (((size_t)b0i * H_ + h) * N_ + n0i) * D_ + d) =
                        make_float2(c[mf][nf][0], c[mf][nf][1]);
                    *(float2*)(dst + (((size_t)b1i * H_ + h) * N_ + n1i) * D_ + d) =
                        make_float2(c[mf][nf][2], c[mf][nf][3]);
                }
            } else {
                float bx = bias[gcol], by = bias[gcol + 1];
                *(float2*)(out + (size_t)r0g * 1024 + gcol) =
                    make_float2(c[mf][nf][0] + bx, c[mf][nf][1] + by);
                *(float2*)(out + (size_t)r1g * 1024 + gcol) =
                    make_float2(c[mf][nf][2] + bx, c[mf][nf][3] + by);
            }
        }
    }
}

// ================= RMSNorm + RoPE: q -> fp16 hi/lo, k -> rna fp16 =================
__global__ __launch_bounds__(256) void norm_rope(const float* __restrict__ qn_w,
                                                 const float* __restrict__ kn_w,
                                                 const float* __restrict__ fc,
                                                 const float* __restrict__ fs) {
    int gw = (blockIdx.x * 256 + threadIdx.x) >> 5;
    int lane = threadIdx.x & 31;
    const int half = B_ * H_ * N_;
    const float* buf; const float* w; int r; bool isk;
    if (gw < half) { buf = g_q; w = qn_w; r = gw; isk = false; }
    else           { buf = g_k; w = kn_w; r = gw - half; isk = true; }
    int n = r & (N_ - 1);
    float2 v = *(const float2*)(buf + (size_t)r * D_ + lane * 2);
    float ss = v.x * v.x + v.y * v.y;
    #pragma unroll
    for (int o = 16; o; o >>= 1) ss += __shfl_xor_sync(0xffffffffu, ss, o);
    float rinv = rsqrtf(ss * (1.0f / D_) + 1e-6f);
    float a = v.x * rinv * w[lane * 2];
    float b = v.y * rinv * w[lane * 2 + 1];
    const float* fcp = fc + n * D_ + lane * 2;
    const float* fsp = fs + n * D_ + lane * 2;
    float c0 = fcp[0], c1 = fcp[1], s0 = fsp[0], s1 = fsp[1];
    float o0 = a * c0 - b * s0, o1 = b * c1 + a * s1;
    if (!isk) {
        uint32_t h, l; splith2(o0, o1, h, l);
        ((uint32_t*)g_qh)[r * 32 + lane] = h;
        ((uint32_t*)g_ql)[r * 32 + lane] = l;
    } else {
        ((uint32_t*)g_k16)[r * 32 + lane] = pkh2(o0, o1);
    }
}

// ================= flash attention, fp16 mma: 2-term S, 1-term PV =================
// Grid (N/128, B*H). 256 thr, 8 warps; warp w owns q rows [qt*128+16w, +16).
// ||q||=||k||=8 after rmsnorm => |s*scale| <= 8: static softmax, no max tracking.
// l accumulates the ROUNDED P (exact reweighting). Strides 72 halves: conflict-free.
__global__ __launch_bounds__(256, 1) void flash_attn_f16() {
    extern __shared__ __half smh[];
    __half* Ks  = smh;                     // [2][64][72]
    __half* Vt  = smh + 2 * 64 * 72;       // [2][64][72]
    __half* PsB = smh + 4 * 64 * 72;       // [8][16][72]
    const uint32_t sK = smem_u32(Ks), sV = smem_u32(Vt);
    const int tid = threadIdx.x;
    const int wid = tid >> 5, lane = tid & 31;
    const int gid = lane >> 2, tig = lane & 3;
    __half* Ps = PsB + wid * 16 * 72;      // warp-private

    const int qt = blockIdx.x, bh = blockIdx.y;
    const int qrow0 = qt * 128 + wid * 16;
    const float SC2 = 0.125f * 1.44269504088896f;   // scale * log2(e)

    // Q fragments (4 k16 slabs over D=64), hi and lo
    uint32_t aqh[4][4], aql[4][4];
    {
        const __half* Qh = g_qh + ((size_t)bh * N_ + qrow0) * 64;
        const __half* Ql = g_ql + ((size_t)bh * N_ + qrow0) * 64;
        #pragma unroll
        for (int ks = 0; ks < 4; ks++) {
            int base = gid * 64 + ks * 16 + 2 * tig;
            aqh[ks][0] = *(const uint32_t*)(Qh + base);
            aqh[ks][1] = *(const uint32_t*)(Qh + base + 8 * 64);
            aqh[ks][2] = *(const uint32_t*)(Qh + base + 8);
            aqh[ks][3] = *(const uint32_t*)(Qh + base + 8 * 64 + 8);
            aql[ks][0] = *(const uint32_t*)(Ql + base);
            aql[ks][1] = *(const uint32_t*)(Ql + base + 8 * 64);
            aql[ks][2] = *(const uint32_t*)(Ql + base + 8);
            aql[ks][3] = *(const uint32_t*)(Ql + base + 8 * 64 + 8);
        }
    }

    float lsum0 = 0.f, lsum1 = 0.f;
    float o[8][4];
    #pragma unroll
    for (int nf = 0; nf < 8; nf++)
        #pragma unroll
        for (int r = 0; r < 4; r++) o[nf][r] = 0.f;

    auto issueKV = [&](int t) {
        const int buf = t & 1;
        #pragma unroll
        for (int i = 0; i < 2; i++) {
            int cc = tid + i * 256;               // 0..511
            int r = cc >> 3, off = (cc & 7) * 8;
            cp16(sK + (((buf * 64 + r) * 72 + off) << 1),
                 g_k16 + ((size_t)bh * 2048 + t * 64 + r) * 64 + off);
            cp16(sV + (((buf * 64 + r) * 72 + off) << 1),
                 g_vt16 + ((size_t)bh * 64 + r) * 2048 + t * 64 + off);
        }
        CP_COMMIT();
    };

    issueKV(0);
    for (int kt = 0; kt < N_ / 64; kt++) {
        if (kt < 31) { issueKV(kt + 1); CP_WAIT(1); }
        else         { CP_WAIT(0); }
        __syncthreads();
        const __half* Kc = Ks + (kt & 1) * (64 * 72);
        const __half* Vc = Vt + (kt & 1) * (64 * 72);

        // S = Q @ K^T (2-term): B-frag = K[key=8nf+gid][d pairs]  (conflict-free)
        float s[8][4];
        #pragma unroll
        for (int nf = 0; nf < 8; nf++) {
            s[nf][0] = s[nf][1] = s[nf][2] = s[nf][3] = 0.f;
            const __half* kb = Kc + (nf * 8 + gid) * 72;
            #pragma unroll
            for (int ks = 0; ks < 4; ks++) {
                uint32_t b0 = *(const uint32_t*)(kb + ks * 16 + 2 * tig);
                uint32_t b1 = *(const uint32_t*)(kb + ks * 16 + 2 * tig + 8);
                mma16(s[nf], aql[ks], b0, b1);
                mma16(s[nf], aqh[ks], b0, b1);
            }
        }

        // static softmax; l from ROUNDED p
        float sum0 = 0.f, sum1 = 0.f;
        #pragma unroll
        for (int nf = 0; nf < 8; nf++) {
            float p0 = exp2a(s[nf][0] * SC2);
            float p1 = exp2a(s[nf][1] * SC2);
            float p2 = exp2a(s[nf][2] * SC2);
            float p3 = exp2a(s[nf][3] * SC2);
            uint32_t u01 = pkh2(p0, p1), u23 = pkh2(p2, p3);
            float2 r01 = uph2(u01), r23 = uph2(u23);
            sum0 += r01.x + r01.y; sum1 += r23.x + r23.y;
            *(uint32_t*)(Ps + gid * 72 + nf * 8 + 2 * tig)       = u01;
            *(uint32_t*)(Ps + (gid + 8) * 72 + nf * 8 + 2 * tig) = u23;
        }
        sum0 += __shfl_xor_sync(0xffffffffu, sum0, 1);
        sum0 += __shfl_xor_sync(0xffffffffu, sum0, 2);
        sum1 += __shfl_xor_sync(0xffffffffu, sum1, 1);
        sum1 += __shfl_xor_sync(0xffffffffu, sum1, 2);
        lsum0 += sum0;
        lsum1 += sum1;
        __syncwarp();

        // O += P @ V (1-term): A-frag from warp-private Ps, B-frag = Vt[d][key pairs]
        #pragma unroll
        for (int ks = 0; ks < 4; ks++) {
            uint32_t ap[4];
            ap[0] = *(const uint32_t*)(Ps + gid * 72 + ks * 16 + 2 * tig);
            ap[1] = *(const uint32_t*)(Ps + (gid + 8) * 72 + ks * 16 + 2 * tig);
            ap[2] = *(const uint32_t*)(Ps + gid * 72 + ks * 16 + 2 * tig + 8);
            ap[3] = *(const uint32_t*)(Ps + (gid + 8) * 72 + ks * 16 + 2 * tig + 8);
            #pragma unroll
            for (int nf = 0; nf < 8; nf++) {
                const __half* vb = Vc + (nf * 8 + gid) * 72 + ks * 16 + 2 * tig;
                mma16(o[nf], ap, *(const uint32_t*)vb, *(const uint32_t*)(vb + 8));
            }
        }
        __syncthreads();   // tile fully consumed before its buffer is refilled
    }

    // epilogue: write fp16 hi/lo in [B,N,C] for proj
    float inv0 = 1.f / lsum0, inv1 = 1.f / lsum1;
    const int bb = bh >> 4, hh = bh & 15;
    #pragma unroll
    for (int nf = 0; nf < 8; nf++) {
        int cc = nf * 8 + 2 * tig;
        size_t i0 = ((size_t)(bb * N_ + qrow0 + gid) * 1024 + hh * 64 + cc) >> 1;
        size_t i1 = ((size_t)(bb * N_ + qrow0 + gid + 8) * 1024 + hh * 64 + cc) >> 1;
        uint32_t h, l;
        splith2(o[nf][0] * inv0, o[nf][1] * inv0, h, l);
        ((uint32_t*)g_oh)[i0] = h; ((uint32_t*)g_ol)[i0] = l;
        splith2(o[nf][2] * inv1, o[nf][3] * inv1, h, l);
        ((uint32_t*)g_oh)[i1] = h; ((uint32_t*)g_ol)[i1] = l;
    }
}

// ================= launch =================
extern "C" void kernel_launch(void* const* d_in, const int* in_sizes, int n_in,
                              void* d_out, int out_size) {
    const float* x      = (const float*)d_in[0];
    const float* w_qkv  = (const float*)d_in[1];
    const float* w_proj = (const float*)d_in[2];
    const float* b_proj = (const float*)d_in[3];
    const float* qn_w   = (const float*)d_in[4];
    const float* kn_w   = (const float*)d_in[5];
    const float* fc     = (const float*)d_in[6];
    const float* fs     = (const float*)d_in[7];
    float* out = (float*)d_out;

    __half *xh, *xl, *wqkvT, *wprojT, *oh, *ol;
    cudaGetSymbolAddress((void**)&xh,     g_xh);
    cudaGetSymbolAddress((void**)&xl,     g_xl);
    cudaGetSymbolAddress((void**)&wqkvT,  g_wqkvT16);
    cudaGetSymbolAddress((void**)&wprojT, g_wprojT16);
    cudaGetSymbolAddress((void**)&oh,     g_oh);
    cudaGetSymbolAddress((void**)&ol,     g_ol);

    split_x<<<QKV_ELEMS / 512, 256>>>(x);
    transpose_w16<<<dim3(96, 32), dim3(32, 8)>>>(w_qkv, wqkvT, 1024, 3072);
    transpose_w16<<<dim3(32, 32), dim3(32, 8)>>>(w_proj, wprojT, 1024, 1024);

    const int gemm_smem = 6 * 128 * 40 * 2;   // 61440 B (Ah,Al,Bh x 2 bufs)
    cudaFuncSetAttribute(gemm_f16<0>, cudaFuncAttributeMaxDynamicSharedMemorySize, gemm_smem);
    cudaFuncSetAttribute(gemm_f16<1>, cudaFuncAttributeMaxDynamicSharedMemorySize, gemm_smem);

    gemm_f16<0><<<dim3(24, 64), 256, gemm_smem>>>(xh, xl, wqkvT, nullptr, nullptr);
    norm_rope<<<32768, 256>>>(qn_w, kn_w, fc, fs);

    const int attn_smem = (4 * 64 * 72 + 8 * 16 * 72) * 2;   // 55296 B
    cudaFuncSetAttribute(flash_attn_f16, cudaFuncAttributeMaxDynamicSharedMemorySize, attn_smem);
    flash_attn_f16<<<dim3(16, 64), 256, attn_smem>>>();

    gemm_f16<1><<<dim3(8, 64), 256, gemm_smem>>>(oh, ol, wprojT, b_proj, out);
}

// round 11
// speedup vs baseline: 4.3183x; 1.0357x over previous
#include <cuda_runtime.h>
#include <cuda_fp16.h>
#include <cstdint>

#define B_ 4
#define N_ 2048
#define C_ 1024
#define H_ 16
#define D_ 64
#define QKV_ELEMS (B_*H_*N_*D_)   // 8388608 == 8192*1024

// Scratch (allocation-free rule: __device__ globals)
__device__ float  g_q[QKV_ELEMS];          // qkv out, pre-norm fp32 [B,H,N,D]
__device__ float  g_k[QKV_ELEMS];
__device__ __half g_qh[QKV_ELEMS];         // post-norm Q hi/lo [B,H,N,D]
__device__ __half g_ql[QKV_ELEMS];
__device__ __half g_k16[QKV_ELEMS];        // post-norm K, rna fp16
__device__ __half g_vt16[QKV_ELEMS];       // V transposed [B,H,D,N], rna fp16
__device__ __half g_oh[QKV_ELEMS];         // attn out hi/lo [B,N,C]
__device__ __half g_ol[QKV_ELEMS];
__device__ __half g_xh[QKV_ELEMS];         // x split hi/lo [B*N, C]
__device__ __half g_xl[QKV_ELEMS];
__device__ __half g_wqkvT16[3072 * 1024];  // w_qkv^T rna fp16
__device__ __half g_wprojT16[1024 * 1024]; // w_proj^T rna fp16

// ---------------- helpers ----------------
__device__ __forceinline__ uint32_t pkh2(float lo, float hi) {
    uint32_t r; asm("cvt.rn.f16x2.f32 %0, %1, %2;" : "=r"(r) : "f"(hi), "f"(lo)); return r;
}
__device__ __forceinline__ float2 uph2(uint32_t v) {
    float2 r;
    asm("{.reg .f16 l, h;\n\t mov.b32 {l, h}, %2;\n\t cvt.f32.f16 %0, l;\n\t cvt.f32.f16 %1, h;}"
        : "=f"(r.x), "=f"(r.y) : "r"(v));
    return r;
}
// split pair (a0,a1) into packed fp16 hi and packed fp16 residual-lo
__device__ __forceinline__ void splith2(float a0, float a1, uint32_t& h, uint32_t& l) {
    h = pkh2(a0, a1);
    float2 hf = uph2(h);
    l = pkh2(a0 - hf.x, a1 - hf.y);
}
__device__ __forceinline__ float exp2a(float x) {
    float r; asm("ex2.approx.f32 %0, %1;" : "=f"(r) : "f"(x)); return r;
}
__device__ __forceinline__ uint32_t smem_u32(const void* p) {
    uint32_t a;
    asm("{ .reg .u64 t; cvta.to.shared.u64 t, %1; cvt.u32.u64 %0, t; }" : "=r"(a) : "l"(p));
    return a;
}
__device__ __forceinline__ void cp16(uint32_t dst, const void* src) {
    asm volatile("cp.async.cg.shared.global [%0], [%1], 16;" :: "r"(dst), "l"(src));
}
#define CP_COMMIT() asm volatile("cp.async.commit_group;" ::: "memory")
#define CP_WAIT(n)  asm volatile("cp.async.wait_group %0;" :: "n"(n) : "memory")

// m16n8k16 fp16 mma, fp32 accum: D += A*B. A: 4 b32 (f16x2), B: 2 b32, C/D: 4 f32.
__device__ __forceinline__ void mma16(float* d, const uint32_t* a, uint32_t b0, uint32_t b1) {
    asm volatile(
        "mma.sync.aligned.m16n8k16.row.col.f32.f16.f16.f32 "
        "{%0,%1,%2,%3}, {%4,%5,%6,%7}, {%8,%9}, {%0,%1,%2,%3};"
        : "+f"(d[0]), "+f"(d[1]), "+f"(d[2]), "+f"(d[3])
        : "r"(a[0]), "r"(a[1]), "r"(a[2]), "r"(a[3]), "r"(b0), "r"(b1));
}

// ================= prep: split x into fp16 hi/lo =================
__global__ __launch_bounds__(256) void split_x(const float* __restrict__ x) {
    int i = blockIdx.x * 256 + threadIdx.x;     // pair index, 4.2M total
    float2 v = *(const float2*)(x + (size_t)i * 2);
    uint32_t h, l; splith2(v.x, v.y, h, l);
    ((uint32_t*)g_xh)[i] = h;
    ((uint32_t*)g_xl)[i] = l;
}

// ================= weight transpose: dst[c][r] = rna_fp16(src[r][c]) =================
__global__ __launch_bounds__(256) void transpose_w16(const float* __restrict__ src,
                                                     __half* __restrict__ dst,
                                                     int R, int Ccols) {
    __shared__ float t[32][33];
    int bx = blockIdx.x * 32, by = blockIdx.y * 32;
    int tx = threadIdx.x, ty = threadIdx.y;      // 32 x 8
    #pragma unroll
    for (int i = 0; i < 32; i += 8)
        t[ty + i][tx] = src[(size_t)(by + ty + i) * Ccols + bx + tx];
    __syncthreads();
    #pragma unroll
    for (int i = 0; i < 32; i += 8)
        dst[(size_t)(bx + ty + i) * R + by + tx] = __float2half_rn(t[tx][ty + i]);
}

// ================= fp16 2-term mma GEMM, 3-stage cp.async, 1 sync/tile =================
// C[M,NN] = (Ah+Al)[M,1024] @ Bh[NN,1024]^T ; BM=BN=128, BK=32 (2 k16 slabs).
// MODE 0: qkv (q,k fp32 scatter; v -> g_vt16 transposed) ; MODE 1: proj (bias + out)
template<int MODE>
__global__ __launch_bounds__(256, 2) void gemm_f16(const __half* __restrict__ Agh,
                                                   const __half* __restrict__ Agl,
                                                   const __half* __restrict__ Bgh,
                                                   const float* __restrict__ bias,
                                                   float* __restrict__ out) {
    extern __shared__ __half gsm[];
    __half* Ahs = gsm;                      // [3][128][40]
    __half* Als = gsm + 3 * 128 * 40;
    __half* Bhs = gsm + 6 * 128 * 40;
    const uint32_t sAh = smem_u32(Ahs), sAl = smem_u32(Als), sBh = smem_u32(Bhs);
    const int tid = threadIdx.x;
    const int wid = tid >> 5, lane = tid & 31;
    const int gid = lane >> 2, tig = lane & 3;
    const int wm = wid & 1, wn = wid >> 1;       // 2 x 4 warp grid
    const int bn = blockIdx.x, bm = blockIdx.y;

    float c[4][4][4];
    #pragma unroll
    for (int mf = 0; mf < 4; mf++)
        #pragma unroll
        for (int nf = 0; nf < 4; nf++)
            #pragma unroll
            for (int r = 0; r < 4; r++) c[mf][nf][r] = 0.f;

    const __half* Ah0 = Agh + (size_t)(bm * 128) * 1024;
    const __half* Al0 = Agl + (size_t)(bm * 128) * 1024;
    const __half* Bh0 = Bgh + (size_t)(bn * 128) * 1024;
    const int lr = tid >> 2, lc = (tid & 3) * 8;   // loader: 64 row-pairs, 8-half chunks

    auto issue = [&](int t) {
        const int buf = t % 3;
        #pragma unroll
        for (int it = 0; it < 2; it++) {
            int r = lr + it * 64;
            uint32_t so = ((buf * 128 + r) * 40 + lc) * 2;
            size_t go = (size_t)r * 1024 + t * 32 + lc;
            cp16(sAh + so, Ah0 + go);
            cp16(sAl + so, Al0 + go);
            cp16(sBh + so, Bh0 + go);
        }
        CP_COMMIT();
    };

    issue(0); issue(1);
    for (int t = 0; t < 32; t++) {
        if (t < 31) { CP_WAIT(1); }   // pending {t, t+1} -> tile t landed
        else        { CP_WAIT(0); }   // final tile: drain fully
        __syncthreads();              // orders iter t-1 reads before reusing buf (t+2)%3
        if (t + 2 < 32) issue(t + 2);
        const int cb = t % 3;
        const __half* Ab = Ahs + cb * (128 * 40);
        const __half* Lb = Als + cb * (128 * 40);
        const __half* Bb = Bhs + cb * (128 * 40);
        #pragma unroll
        for (int ks = 0; ks < 2; ks++) {
            uint32_t bh[4][2];
            #pragma unroll
            for (int nf = 0; nf < 4; nf++) {
                const __half* bp = Bb + (wn * 32 + nf * 8 + gid) * 40 + ks * 16 + 2 * tig;
                bh[nf][0] = *(const uint32_t*)bp;
                bh[nf][1] = *(const uint32_t*)(bp + 8);
            }
            #pragma unroll
            for (int mf = 0; mf < 4; mf++) {
                const __half* ap = Ab + (wm * 64 + mf * 16 + gid) * 40 + ks * 16 + 2 * tig;
                const __half* lp = Lb + (wm * 64 + mf * 16 + gid) * 40 + ks * 16 + 2 * tig;
                uint32_t ah[4] = { *(const uint32_t*)ap, *(const uint32_t*)(ap + 8 * 40),
                                   *(const uint32_t*)(ap + 8), *(const uint32_t*)(ap + 8 * 40 + 8) };
                uint32_t al[4] = { *(const uint32_t*)lp, *(const uint32_t*)(lp + 8 * 40),
                                   *(const uint32_t*)(lp + 8), *(const uint32_t*)(lp + 8 * 40 + 8) };
                #pragma unroll
                for (int nf = 0; nf < 4; nf++) {
                    mma16(c[mf][nf], al, bh[nf][0], bh[nf][1]);
                    mma16(c[mf][nf], ah, bh[nf][0], bh[nf][1]);
                }
            }
        }
    }

    // epilogue: thread holds rows (r0, r0+8), cols (gcol, gcol+1) per fragment
    #pragma unroll
    for (int mf = 0; mf < 4; mf++) {
        int r0g = bm * 128 + wm * 64 + mf * 16 + gid;
        int r1g = r0g + 8;
        #pragma unroll
        for (int nf = 0; nf < 4; nf++) {
            int gcol = bn * 128 + wn * 32 + nf * 8 + 2 * tig;
            if (MODE == 0) {
                int which = gcol >> 10, h = (gcol >> 6) & 15, d = gcol & 63;
                int b0i = r0g >> 11, n0i = r0g & 2047;
                int b1i = r1g >> 11, n1i = r1g & 2047;
                if (which == 2) {    // v: rna fp16, transposed [B,H,D,N]
                    size_t vb0 = ((size_t)(b0i * H_ + h)) * 64;
                    size_t vb1 = ((size_t)(b1i * H_ + h)) * 64;
                    g_vt16[(vb0 + d) * 2048 + n0i]     = __float2half_rn(c[mf][nf][0]);
                    g_vt16[(vb0 + d + 1) * 2048 + n0i] = __float2half_rn(c[mf][nf][1]);
                    g_vt16[(vb1 + d) * 2048 + n1i]     = __float2half_rn(c[mf][nf][2]);
                    g_vt16[(vb1 + d + 1) * 2048 + n1i] = __float2half_rn(c[mf][nf][3]);
                } else {
                    float* dst = which == 0 ? g_q : g_k;
                    *(float2*)(dst + (((size_t)b0i * H_ + h) * N_ + n0i) * D_ + d) =
                        make_float2(c[mf][nf][0], c[mf][nf][1]);
                    *(float2*)(dst + (((size_t)b1i * H_ + h) * N_ + n1i) * D_ + d) =
                        make_float2(c[mf][nf][2], c[mf][nf][3]);
                }
            } else {
                float bx = bias[gcol], by = bias[gcol + 1];
                *(float2*)(out + (size_t)r0g * 1024 + gcol) =
                    make_float2(c[mf][nf][0] + bx, c[mf][nf][1] + by);
                *(float2*)(out + (size_t)r1g * 1024 + gcol) =
                    make_float2(c[mf][nf][2] + bx, c[mf][nf][3] + by);
            }
        }
    }
}

// ================= RMSNorm + RoPE: q -> fp16 hi/lo, k -> rna fp16 =================
__global__ __launch_bounds__(256) void norm_rope(const float* __restrict__ qn_w,
                                                 const float* __restrict__ kn_w,
                                                 const float* __restrict__ fc,
                                                 const float* __restrict__ fs) {
    int gw = (blockIdx.x * 256 + threadIdx.x) >> 5;
    int lane = threadIdx.x & 31;
    const int half = B_ * H_ * N_;
    const float* buf; const float* w; int r; bool isk;
    if (gw < half) { buf = g_q; w = qn_w; r = gw; isk = false; }
    else           { buf = g_k; w = kn_w; r = gw - half; isk = true; }
    int n = r & (N_ - 1);
    float2 v = *(const float2*)(buf + (size_t)r * D_ + lane * 2);
    float ss = v.x * v.x + v.y * v.y;
    #pragma unroll
    for (int o = 16; o; o >>= 1) ss += __shfl_xor_sync(0xffffffffu, ss, o);
    float rinv = rsqrtf(ss * (1.0f / D_) + 1e-6f);
    float a = v.x * rinv * w[lane * 2];
    float b = v.y * rinv * w[lane * 2 + 1];
    const float* fcp = fc + n * D_ + lane * 2;
    const float* fsp = fs + n * D_ + lane * 2;
    float c0 = fcp[0], c1 = fcp[1], s0 = fsp[0], s1 = fsp[1];
    float o0 = a * c0 - b * s0, o1 = b * c1 + a * s1;
    if (!isk) {
        uint32_t h, l; splith2(o0, o1, h, l);
        ((uint32_t*)g_qh)[r * 32 + lane] = h;
        ((uint32_t*)g_ql)[r * 32 + lane] = l;
    } else {
        ((uint32_t*)g_k16)[r * 32 + lane] = pkh2(o0, o1);
    }
}

// ================= flash attention, fp16 mma: 3-stage pipeline, 2 CTAs/SM =================
// Grid (N/128, B*H). 256 thr, 8 warps; warp w owns q rows [qt*128+16w, +16).
// ||q||=||k||=8 after rmsnorm => |s*scale| <= 8: static softmax, no max tracking.
// l accumulates the ROUNDED P (exact reweighting). Strides 72 halves: conflict-free.
__global__ __launch_bounds__(256, 2) void flash_attn_f16() {
    extern __shared__ __half smh[];
    __half* Ks  = smh;                     // [3][64][72]
    __half* Vt  = smh + 3 * 64 * 72;       // [3][64][72]
    __half* PsB = smh + 6 * 64 * 72;       // [8][16][72]
    const uint32_t sK = smem_u32(Ks), sV = smem_u32(Vt);
    const int tid = threadIdx.x;
    const int wid = tid >> 5, lane = tid & 31;
    const int gid = lane >> 2, tig = lane & 3;
    __half* Ps = PsB + wid * 16 * 72;      // warp-private

    const int qt = blockIdx.x, bh = blockIdx.y;
    const int qrow0 = qt * 128 + wid * 16;
    const float SC2 = 0.125f * 1.44269504088896f;   // scale * log2(e)

    // Q fragments (4 k16 slabs over D=64), hi and lo
    uint32_t aqh[4][4], aql[4][4];
    {
        const __half* Qh = g_qh + ((size_t)bh * N_ + qrow0) * 64;
        const __half* Ql = g_ql + ((size_t)bh * N_ + qrow0) * 64;
        #pragma unroll
        for (int ks = 0; ks < 4; ks++) {
            int base = gid * 64 + ks * 16 + 2 * tig;
            aqh[ks][0] = *(const uint32_t*)(Qh + base);
            aqh[ks][1] = *(const uint32_t*)(Qh + base + 8 * 64);
            aqh[ks][2] = *(const uint32_t*)(Qh + base + 8);
            aqh[ks][3] = *(const uint32_t*)(Qh + base + 8 * 64 + 8);
            aql[ks][0] = *(const uint32_t*)(Ql + base);
            aql[ks][1] = *(const uint32_t*)(Ql + base + 8 * 64);
            aql[ks][2] = *(const uint32_t*)(Ql + base + 8);
            aql[ks][3] = *(const uint32_t*)(Ql + base + 8 * 64 + 8);
        }
    }

    float lsum0 = 0.f, lsum1 = 0.f;
    float o[8][4];
    #pragma unroll
    for (int nf = 0; nf < 8; nf++)
        #pragma unroll
        for (int r = 0; r < 4; r++) o[nf][r] = 0.f;

    auto issueKV = [&](int t) {
        const int buf = t % 3;
        #pragma unroll
        for (int i = 0; i < 2; i++) {
            int cc = tid + i * 256;               // 0..511
            int r = cc >> 3, off = (cc & 7) * 8;
            cp16(sK + (((buf * 64 + r) * 72 + off) << 1),
                 g_k16 + ((size_t)bh * 2048 + t * 64 + r) * 64 + off);
            cp16(sV + (((buf * 64 + r) * 72 + off) << 1),
                 g_vt16 + ((size_t)bh * 64 + r) * 2048 + t * 64 + off);
        }
        CP_COMMIT();
    };

    issueKV(0); issueKV(1);
    for (int kt = 0; kt < N_ / 64; kt++) {
        if (kt < 31) { CP_WAIT(1); }
        else         { CP_WAIT(0); }
        __syncthreads();              // orders iter kt-1 reads before reusing buf (kt+2)%3
        if (kt + 2 < 32) issueKV(kt + 2);
        const int cb = kt % 3;
        const __half* Kc = Ks + cb * (64 * 72);
        const __half* Vc = Vt + cb * (64 * 72);

        // S = Q @ K^T (2-term): B-frag = K[key=8nf+gid][d pairs]  (conflict-free)
        float s[8][4];
        #pragma unroll
        for (int nf = 0; nf < 8; nf++) {
            s[nf][0] = s[nf][1] = s[nf][2] = s[nf][3] = 0.f;
            const __half* kb = Kc + (nf * 8 + gid) * 72;
            #pragma unroll
            for (int ks = 0; ks < 4; ks++) {
                uint32_t b0 = *(const uint32_t*)(kb + ks * 16 + 2 * tig);
                uint32_t b1 = *(const uint32_t*)(kb + ks * 16 + 2 * tig + 8);
                mma16(s[nf], aql[ks], b0, b1);
                mma16(s[nf], aqh[ks], b0, b1);
            }
        }

        // static softmax; l from ROUNDED p
        float sum0 = 0.f, sum1 = 0.f;
        #pragma unroll
        for (int nf = 0; nf < 8; nf++) {
            float p0 = exp2a(s[nf][0] * SC2);
            float p1 = exp2a(s[nf][1] * SC2);
            float p2 = exp2a(s[nf][2] * SC2);
            float p3 = exp2a(s[nf][3] * SC2);
            uint32_t u01 = pkh2(p0, p1), u23 = pkh2(p2, p3);
            float2 r01 = uph2(u01), r23 = uph2(u23);
            sum0 += r01.x + r01.y; sum1 += r23.x + r23.y;
            *(uint32_t*)(Ps + gid * 72 + nf * 8 + 2 * tig)       = u01;
            *(uint32_t*)(Ps + (gid + 8) * 72 + nf * 8 + 2 * tig) = u23;
        }
        sum0 += __shfl_xor_sync(0xffffffffu, sum0, 1);
        sum0 += __shfl_xor_sync(0xffffffffu, sum0, 2);
        sum1 += __shfl_xor_sync(0xffffffffu, sum1, 1);
        sum1 += __shfl_xor_sync(0xffffffffu, sum1, 2);
        lsum0 += sum0;
        lsum1 += sum1;
        __syncwarp();

        // O += P @ V (1-term): A-frag from warp-private Ps, B-frag = Vt[d][key pairs]
        #pragma unroll
        for (int ks = 0; ks < 4; ks++) {
            uint32_t ap[4];
            ap[0] = *(const uint32_t*)(Ps + gid * 72 + ks * 16 + 2 * tig);
            ap[1] = *(const uint32_t*)(Ps + (gid + 8) * 72 + ks * 16 + 2 * tig);
            ap[2] = *(const uint32_t*)(Ps + gid * 72 + ks * 16 + 2 * tig + 8);
            ap[3] = *(const uint32_t*)(Ps + (gid + 8) * 72 + ks * 16 + 2 * tig + 8);
            #pragma unroll
            for (int nf = 0; nf < 8; nf++) {
                const __half* vb = Vc + (nf * 8 + gid) * 72 + ks * 16 + 2 * tig;
                mma16(o[nf], ap, *(const uint32_t*)vb, *(const uint32_t*)(vb + 8));
            }
        }
        __syncwarp();   // Ps reads done before next tile's stores (warp-private)
    }

    // epilogue: write fp16 hi/lo in [B,N,C] for proj
    float inv0 = 1.f / lsum0, inv1 = 1.f / lsum1;
    const int bb = bh >> 4, hh = bh & 15;
    #pragma unroll
    for (int nf = 0; nf < 8; nf++) {
        int cc = nf * 8 + 2 * tig;
        size_t i0 = ((size_t)(bb * N_ + qrow0 + gid) * 1024 + hh * 64 + cc) >> 1;
        size_t i1 = ((size_t)(bb * N_ + qrow0 + gid + 8) * 1024 + hh * 64 + cc) >> 1;
        uint32_t h, l;
        splith2(o[nf][0] * inv0, o[nf][1] * inv0, h, l);
        ((uint32_t*)g_oh)[i0] = h; ((uint32_t*)g_ol)[i0] = l;
        splith2(o[nf][2] * inv1, o[nf][3] * inv1, h, l);
        ((uint32_t*)g_oh)[i1] = h; ((uint32_t*)g_ol)[i1] = l;
    }
}

// ================= launch =================
extern "C" void kernel_launch(void* const* d_in, const int* in_sizes, int n_in,
                              void* d_out, int out_size) {
    const float* x      = (const float*)d_in[0];
    const float* w_qkv  = (const float*)d_in[1];
    const float* w_proj = (const float*)d_in[2];
    const float* b_proj = (const float*)d_in[3];
    const float* qn_w   = (const float*)d_in[4];
    const float* kn_w   = (const float*)d_in[5];
    const float* fc     = (const float*)d_in[6];
    const float* fs     = (const float*)d_in[7];
    float* out = (float*)d_out;

    __half *xh, *xl, *wqkvT, *wprojT, *oh, *ol;
    cudaGetSymbolAddress((void**)&xh,     g_xh);
    cudaGetSymbolAddress((void**)&xl,     g_xl);
    cudaGetSymbolAddress((void**)&wqkvT,  g_wqkvT16);
    cudaGetSymbolAddress((void**)&wprojT, g_wprojT16);
    cudaGetSymbolAddress((void**)&oh,     g_oh);
    cudaGetSymbolAddress((void**)&ol,     g_ol);

    split_x<<<QKV_ELEMS / 512, 256>>>(x);
    transpose_w16<<<dim3(96, 32), dim3(32, 8)>>>(w_qkv, wqkvT, 1024, 3072);
    transpose_w16<<<dim3(32, 32), dim3(32, 8)>>>(w_proj, wprojT, 1024, 1024);

    const int gemm_smem = 9 * 128 * 40 * 2;   // 92160 B (Ah,Al,Bh x 3 stages)
    cudaFuncSetAttribute(gemm_f16<0>, cudaFuncAttributeMaxDynamicSharedMemorySize, gemm_smem);
    cudaFuncSetAttribute(gemm_f16<1>, cudaFuncAttributeMaxDynamicSharedMemorySize, gemm_smem);

    gemm_f16<0><<<dim3(24, 64), 256, gemm_smem>>>(xh, xl, wqkvT, nullptr, nullptr);
    norm_rope<<<32768, 256>>>(qn_w, kn_w, fc, fs);

    const int attn_smem = (6 * 64 * 72 + 8 * 16 * 72) * 2;   // 73728 B (3-stage K/V + Ps)
    cudaFuncSetAttribute(flash_attn_f16, cudaFuncAttributeMaxDynamicSharedMemorySize, attn_smem);
    flash_attn_f16<<<dim3(16, 64), 256, attn_smem>>>();

    gemm_f16<1><<<dim3(8, 64), 256, gemm_smem>>>(oh, ol, wprojT, b_proj, out);
}

// round 12
// speedup vs baseline: 4.6529x; 1.0775x over previous
#include <cuda_runtime.h>
#include <cuda_fp16.h>
#include <cstdint>

#define B_ 4
#define N_ 2048
#define C_ 1024
#define H_ 16
#define D_ 64
#define QKV_ELEMS (B_*H_*N_*D_)   // 8388608 == 8192*1024

// Scratch (allocation-free rule: __device__ globals)
__device__ float  g_q[QKV_ELEMS];          // qkv out, pre-norm fp32 [B,H,N,D]
__device__ float  g_k[QKV_ELEMS];
__device__ __half g_qh[QKV_ELEMS];         // post-norm Q hi/lo [B,H,N,D]
__device__ __half g_ql[QKV_ELEMS];
__device__ __half g_k16[QKV_ELEMS];        // post-norm K, rna fp16
__device__ __half g_vt16[QKV_ELEMS];       // V transposed [B,H,D,N], rna fp16
__device__ __half g_oh[QKV_ELEMS];         // attn out hi/lo [B,N,C]
__device__ __half g_ol[QKV_ELEMS];
__device__ __half g_xh[QKV_ELEMS];         // x split hi/lo [B*N, C]
__device__ __half g_xl[QKV_ELEMS];
__device__ __half g_wqkvT16[3072 * 1024];  // w_qkv^T rna fp16
__device__ __half g_wprojT16[1024 * 1024]; // w_proj^T rna fp16

// ---------------- helpers ----------------
__device__ __forceinline__ uint32_t pkh2(float lo, float hi) {
    uint32_t r; asm("cvt.rn.f16x2.f32 %0, %1, %2;" : "=r"(r) : "f"(hi), "f"(lo)); return r;
}
__device__ __forceinline__ float2 uph2(uint32_t v) {
    float2 r;
    asm("{.reg .f16 l, h;\n\t mov.b32 {l, h}, %2;\n\t cvt.f32.f16 %0, l;\n\t cvt.f32.f16 %1, h;}"
        : "=f"(r.x), "=f"(r.y) : "r"(v));
    return r;
}
// split pair (a0,a1) into packed fp16 hi and packed fp16 residual-lo
__device__ __forceinline__ void splith2(float a0, float a1, uint32_t& h, uint32_t& l) {
    h = pkh2(a0, a1);
    float2 hf = uph2(h);
    l = pkh2(a0 - hf.x, a1 - hf.y);
}
__device__ __forceinline__ float exp2a(float x) {
    float r; asm("ex2.approx.f32 %0, %1;" : "=f"(r) : "f"(x)); return r;
}
__device__ __forceinline__ uint32_t smem_u32(const void* p) {
    uint32_t a;
    asm("{ .reg .u64 t; cvta.to.shared.u64 t, %1; cvt.u32.u64 %0, t; }" : "=r"(a) : "l"(p));
    return a;
}
__device__ __forceinline__ void cp16(uint32_t dst, const void* src) {
    asm volatile("cp.async.cg.shared.global [%0], [%1], 16;" :: "r"(dst), "l"(src));
}
#define CP_COMMIT() asm volatile("cp.async.commit_group;" ::: "memory")
#define CP_WAIT(n)  asm volatile("cp.async.wait_group %0;" :: "n"(n) : "memory")

// ldmatrix x4: four 8x8 b16 matrices -> 4 u32/thread
__device__ __forceinline__ void ldsm_x4(uint32_t* r, uint32_t addr) {
    asm volatile("ldmatrix.sync.aligned.m8n8.x4.shared.b16 {%0,%1,%2,%3}, [%4];"
        : "=r"(r[0]), "=r"(r[1]), "=r"(r[2]), "=r"(r[3]) : "r"(addr));
}

// m16n8k16 fp16 mma, fp32 accum: D += A*B. A: 4 b32 (f16x2), B: 2 b32, C/D: 4 f32.
__device__ __forceinline__ void mma16(float* d, const uint32_t* a, uint32_t b0, uint32_t b1) {
    asm volatile(
        "mma.sync.aligned.m16n8k16.row.col.f32.f16.f16.f32 "
        "{%0,%1,%2,%3}, {%4,%5,%6,%7}, {%8,%9}, {%0,%1,%2,%3};"
        : "+f"(d[0]), "+f"(d[1]), "+f"(d[2]), "+f"(d[3])
        : "r"(a[0]), "r"(a[1]), "r"(a[2]), "r"(a[3]), "r"(b0), "r"(b1));
}

// ================= prep: split x into fp16 hi/lo =================
__global__ __launch_bounds__(256) void split_x(const float* __restrict__ x) {
    int i = blockIdx.x * 256 + threadIdx.x;     // pair index, 4.2M total
    float2 v = *(const float2*)(x + (size_t)i * 2);
    uint32_t h, l; splith2(v.x, v.y, h, l);
    ((uint32_t*)g_xh)[i] = h;
    ((uint32_t*)g_xl)[i] = l;
}

// ================= weight transpose: dst[c][r] = rna_fp16(src[r][c]) =================
__global__ __launch_bounds__(256) void transpose_w16(const float* __restrict__ src,
                                                     __half* __restrict__ dst,
                                                     int R, int Ccols) {
    __shared__ float t[32][33];
    int bx = blockIdx.x * 32, by = blockIdx.y * 32;
    int tx = threadIdx.x, ty = threadIdx.y;      // 32 x 8
    #pragma unroll
    for (int i = 0; i < 32; i += 8)
        t[ty + i][tx] = src[(size_t)(by + ty + i) * Ccols + bx + tx];
    __syncthreads();
    #pragma unroll
    for (int i = 0; i < 32; i += 8)
        dst[(size_t)(bx + ty + i) * R + by + tx] = __float2half_rn(t[tx][ty + i]);
}

// ================= fp16 2-term mma GEMM, 3-stage cp.async, ldmatrix frags =================
// C[M,NN] = (Ah+Al)[M,1024] @ Bh[NN,1024]^T ; BM=BN=128, BK=32 (2 k16 slabs).
// MODE 0: qkv (q,k fp32 scatter; v -> g_vt16 transposed) ; MODE 1: proj (bias + out)
template<int MODE>
__global__ __launch_bounds__(256, 2) void gemm_f16(const __half* __restrict__ Agh,
                                                   const __half* __restrict__ Agl,
                                                   const __half* __restrict__ Bgh,
                                                   const float* __restrict__ bias,
                                                   float* __restrict__ out) {
    extern __shared__ __half gsm[];
    __half* Ahs = gsm;                      // [3][128][40]
    __half* Als = gsm + 3 * 128 * 40;
    __half* Bhs = gsm + 6 * 128 * 40;
    const uint32_t sAh = smem_u32(Ahs), sAl = smem_u32(Als), sBh = smem_u32(Bhs);
    const int tid = threadIdx.x;
    const int wid = tid >> 5, lane = tid & 31;
    const int gid = lane >> 2, tig = lane & 3;
    const int wm = wid & 1, wn = wid >> 1;       // 2 x 4 warp grid
    const int bn = blockIdx.x, bm = blockIdx.y;

    // ldmatrix lane offsets (halves)
    const int rA = (lane & 7) + ((lane >> 3) & 1) * 8;   // A-frag row
    const int cA = ((lane >> 4) & 1) * 8;                // A-frag col
    const int rB = (lane & 7) + ((lane >> 4) & 1) * 8;   // B-frag row
    const int cB = ((lane >> 3) & 1) * 8;                // B-frag col
    const uint32_t baseA = (wm * 64 + rA) * 40 + cA;
    const uint32_t baseB = (wn * 32 + rB) * 40 + cB;

    float c[4][4][4];
    #pragma unroll
    for (int mf = 0; mf < 4; mf++)
        #pragma unroll
        for (int nf = 0; nf < 4; nf++)
            #pragma unroll
            for (int r = 0; r < 4; r++) c[mf][nf][r] = 0.f;

    const __half* Ah0 = Agh + (size_t)(bm * 128) * 1024;
    const __half* Al0 = Agl + (size_t)(bm * 128) * 1024;
    const __half* Bh0 = Bgh + (size_t)(bn * 128) * 1024;
    const int lr = tid >> 2, lc = (tid & 3) * 8;   // loader: 64 row-pairs, 8-half chunks

    auto issue = [&](int t) {
        const int buf = t % 3;
        #pragma unroll
        for (int it = 0; it < 2; it++) {
            int r = lr + it * 64;
            uint32_t so = ((buf * 128 + r) * 40 + lc) * 2;
            size_t go = (size_t)r * 1024 + t * 32 + lc;
            cp16(sAh + so, Ah0 + go);
            cp16(sAl + so, Al0 + go);
            cp16(sBh + so, Bh0 + go);
        }
        CP_COMMIT();
    };

    issue(0); issue(1);
    for (int t = 0; t < 32; t++) {
        if (t < 31) { CP_WAIT(1); }   // pending {t, t+1} -> tile t landed
        else        { CP_WAIT(0); }
        __syncthreads();              // orders iter t-1 reads before reusing buf (t+2)%3
        if (t + 2 < 32) issue(t + 2);
        const uint32_t oT = (uint32_t)(t % 3) * (128 * 40 * 2);
        #pragma unroll
        for (int ks = 0; ks < 2; ks++) {
            uint32_t bq[8];
            ldsm_x4(bq + 0, sBh + oT + (baseB + ks * 16) * 2);
            ldsm_x4(bq + 4, sBh + oT + (baseB + 16 * 40 + ks * 16) * 2);
            #pragma unroll
            for (int mf = 0; mf < 4; mf++) {
                uint32_t ah[4], al[4];
                uint32_t ao = oT + (baseA + mf * 16 * 40 + ks * 16) * 2;
                ldsm_x4(ah, sAh + ao);
                ldsm_x4(al, sAl + ao);
                #pragma unroll
                for (int nf = 0; nf < 4; nf++) {
                    mma16(c[mf][nf], al, bq[nf * 2], bq[nf * 2 + 1]);
                    mma16(c[mf][nf], ah, bq[nf * 2], bq[nf * 2 + 1]);
                }
            }
        }
    }

    // epilogue: thread holds rows (r0, r0+8), cols (gcol, gcol+1) per fragment
    #pragma unroll
    for (int mf = 0; mf < 4; mf++) {
        int r0g = bm * 128 + wm * 64 + mf * 16 + gid;
        int r1g = r0g + 8;
        #pragma unroll
        for (int nf = 0; nf < 4; nf++) {
            int gcol = bn * 128 + wn * 32 + nf * 8 + 2 * tig;
            if (MODE == 0) {
                int which = gcol >> 10, h = (gcol >> 6) & 15, d = gcol & 63;
                int b0i = r0g >> 11, n0i = r0g & 2047;
                int b1i = r1g >> 11, n1i = r1g & 2047;
                if (which == 2) {    // v: rna fp16, transposed [B,H,D,N]
                    size_t vb0 = ((size_t)(b0i * H_ + h)) * 64;
                    size_t vb1 = ((size_t)(b1i * H_ + h)) * 64;
                    g_vt16[(vb0 + d) * 2048 + n0i]     = __float2half_rn(c[mf][nf][0]);
                    g_vt16[(vb0 + d + 1) * 2048 + n0i] = __float2half_rn(c[mf][nf][1]);
                    g_vt16[(vb1 + d) * 2048 + n1i]     = __float2half_rn(c[mf][nf][2]);
                    g_vt16[(vb1 + d + 1) * 2048 + n1i] = __float2half_rn(c[mf][nf][3]);
                } else {
                    float* dst = which == 0 ? g_q : g_k;
                    *(float2*)(dst + (((size_t)b0i * H_ + h) * N_ + n0i) * D_ + d) =
                        make_float2(c[mf][nf][0], c[mf][nf][1]);
                    *(float2*)(dst + (((size_t)b1i * H_ + h) * N_ + n1i) * D_ + d) =
                        make_float2(c[mf][nf][2], c[mf][nf][3]);
                }
            } else {
                float bx = bias[gcol], by = bias[gcol + 1];
                *(float2*)(out + (size_t)r0g * 1024 + gcol) =
                    make_float2(c[mf][nf][0] + bx, c[mf][nf][1] + by);
                *(float2*)(out + (size_t)r1g * 1024 + gcol) =
                    make_float2(c[mf][nf][2] + bx, c[mf][nf][3] + by);
            }
        }
    }
}

// ================= RMSNorm + RoPE: q -> fp16 hi/lo, k -> rna fp16 =================
__global__ __launch_bounds__(256) void norm_rope(const float* __restrict__ qn_w,
                                                 const float* __restrict__ kn_w,
                                                 const float* __restrict__ fc,
                                                 const float* __restrict__ fs) {
    int gw = (blockIdx.x * 256 + threadIdx.x) >> 5;
    int lane = threadIdx.x & 31;
    const int half = B_ * H_ * N_;
    const float* buf; const float* w; int r; bool isk;
    if (gw < half) { buf = g_q; w = qn_w; r = gw; isk = false; }
    else           { buf = g_k; w = kn_w; r = gw - half; isk = true; }
    int n = r & (N_ - 1);
    float2 v = *(const float2*)(buf + (size_t)r * D_ + lane * 2);
    float ss = v.x * v.x + v.y * v.y;
    #pragma unroll
    for (int o = 16; o; o >>= 1) ss += __shfl_xor_sync(0xffffffffu, ss, o);
    float rinv = rsqrtf(ss * (1.0f / D_) + 1e-6f);
    float a = v.x * rinv * w[lane * 2];
    float b = v.y * rinv * w[lane * 2 + 1];
    const float* fcp = fc + n * D_ + lane * 2;
    const float* fsp = fs + n * D_ + lane * 2;
    float c0 = fcp[0], c1 = fcp[1], s0 = fsp[0], s1 = fsp[1];
    float o0 = a * c0 - b * s0, o1 = b * c1 + a * s1;
    if (!isk) {
        uint32_t h, l; splith2(o0, o1, h, l);
        ((uint32_t*)g_qh)[r * 32 + lane] = h;
        ((uint32_t*)g_ql)[r * 32 + lane] = l;
    } else {
        ((uint32_t*)g_k16)[r * 32 + lane] = pkh2(o0, o1);
    }
}

// ================= flash attention, fp16 mma + ldmatrix, 3-stage, 2 CTAs/SM =================
// Grid (N/128, B*H). 256 thr, 8 warps; warp w owns q rows [qt*128+16w, +16).
// ||q||=||k||=8 after rmsnorm => |s*scale| <= 8: static softmax, no max tracking.
// l accumulates the ROUNDED P (exact reweighting). Strides 72 halves: conflict-free.
__global__ __launch_bounds__(256, 2) void flash_attn_f16() {
    extern __shared__ __half smh[];
    __half* Ks  = smh;                     // [3][64][72]
    __half* Vt  = smh + 3 * 64 * 72;       // [3][64][72]
    __half* PsB = smh + 6 * 64 * 72;       // [8][16][72]
    const uint32_t sK = smem_u32(Ks), sV = smem_u32(Vt);
    const int tid = threadIdx.x;
    const int wid = tid >> 5, lane = tid & 31;
    const int gid = lane >> 2, tig = lane & 3;
    __half* Ps = PsB + wid * 16 * 72;      // warp-private
    const uint32_t sPs = smem_u32(Ps);

    const int qt = blockIdx.x, bh = blockIdx.y;
    const int qrow0 = qt * 128 + wid * 16;
    const float SC2 = 0.125f * 1.44269504088896f;   // scale * log2(e)

    // ldmatrix lane offsets (halves)
    const int rA = (lane & 7) + ((lane >> 3) & 1) * 8;
    const int cA = ((lane >> 4) & 1) * 8;
    const int rB = (lane & 7) + ((lane >> 4) & 1) * 8;
    const int cB = ((lane >> 3) & 1) * 8;
    const uint32_t baseKV = (uint32_t)(rB * 72 + cB);
    const uint32_t basePa = (uint32_t)(rA * 72 + cA);

    // Q fragments (4 k16 slabs over D=64), hi and lo
    uint32_t aqh[4][4], aql[4][4];
    {
        const __half* Qh = g_qh + ((size_t)bh * N_ + qrow0) * 64;
        const __half* Ql = g_ql + ((size_t)bh * N_ + qrow0) * 64;
        #pragma unroll
        for (int ks = 0; ks < 4; ks++) {
            int base = gid * 64 + ks * 16 + 2 * tig;
            aqh[ks][0] = *(const uint32_t*)(Qh + base);
            aqh[ks][1] = *(const uint32_t*)(Qh + base + 8 * 64);
            aqh[ks][2] = *(const uint32_t*)(Qh + base + 8);
            aqh[ks][3] = *(const uint32_t*)(Qh + base + 8 * 64 + 8);
            aql[ks][0] = *(const uint32_t*)(Ql + base);
            aql[ks][1] = *(const uint32_t*)(Ql + base + 8 * 64);
            aql[ks][2] = *(const uint32_t*)(Ql + base + 8);
            aql[ks][3] = *(const uint32_t*)(Ql + base + 8 * 64 + 8);
        }
    }

    float lsum0 = 0.f, lsum1 = 0.f;
    float o[8][4];
    #pragma unroll
    for (int nf = 0; nf < 8; nf++)
        #pragma unroll
        for (int r = 0; r < 4; r++) o[nf][r] = 0.f;

    auto issueKV = [&](int t) {
        const int buf = t % 3;
        #pragma unroll
        for (int i = 0; i < 2; i++) {
            int cc = tid + i * 256;               // 0..511
            int r = cc >> 3, off = (cc & 7) * 8;
            cp16(sK + (((buf * 64 + r) * 72 + off) << 1),
                 g_k16 + ((size_t)bh * 2048 + t * 64 + r) * 64 + off);
            cp16(sV + (((buf * 64 + r) * 72 + off) << 1),
                 g_vt16 + ((size_t)bh * 64 + r) * 2048 + t * 64 + off);
        }
        CP_COMMIT();
    };

    issueKV(0); issueKV(1);
    for (int kt = 0; kt < N_ / 64; kt++) {
        if (kt < 31) { CP_WAIT(1); }
        else         { CP_WAIT(0); }
        __syncthreads();              // orders iter kt-1 reads before reusing buf (kt+2)%3
        if (kt + 2 < 32) issueKV(kt + 2);
        const uint32_t oKV = (uint32_t)(kt % 3) * (64 * 72 * 2);

        // S = Q @ K^T (2-term): K B-frags via ldmatrix (pairs of nf)
        float s[8][4];
        #pragma unroll
        for (int nf = 0; nf < 8; nf++)
            s[nf][0] = s[nf][1] = s[nf][2] = s[nf][3] = 0.f;
        #pragma unroll
        for (int ks = 0; ks < 4; ks++) {
            #pragma unroll
            for (int nfp = 0; nfp < 4; nfp++) {
                uint32_t kq[4];
                ldsm_x4(kq, sK + oKV + (baseKV + nfp * 16 * 72 + ks * 16) * 2);
                mma16(s[nfp * 2],     aql[ks], kq[0], kq[1]);
                mma16(s[nfp * 2],     aqh[ks], kq[0], kq[1]);
                mma16(s[nfp * 2 + 1], aql[ks], kq[2], kq[3]);
                mma16(s[nfp * 2 + 1], aqh[ks], kq[2], kq[3]);
            }
        }

        // static softmax; l from ROUNDED p
        float sum0 = 0.f, sum1 = 0.f;
        #pragma unroll
        for (int nf = 0; nf < 8; nf++) {
            float p0 = exp2a(s[nf][0] * SC2);
            float p1 = exp2a(s[nf][1] * SC2);
            float p2 = exp2a(s[nf][2] * SC2);
            float p3 = exp2a(s[nf][3] * SC2);
            uint32_t u01 = pkh2(p0, p1), u23 = pkh2(p2, p3);
            float2 r01 = uph2(u01), r23 = uph2(u23);
            sum0 += r01.x + r01.y; sum1 += r23.x + r23.y;
            *(uint32_t*)(Ps + gid * 72 + nf * 8 + 2 * tig)       = u01;
            *(uint32_t*)(Ps + (gid + 8) * 72 + nf * 8 + 2 * tig) = u23;
        }
        sum0 += __shfl_xor_sync(0xffffffffu, sum0, 1);
        sum0 += __shfl_xor_sync(0xffffffffu, sum0, 2);
        sum1 += __shfl_xor_sync(0xffffffffu, sum1, 1);
        sum1 += __shfl_xor_sync(0xffffffffu, sum1, 2);
        lsum0 += sum0;
        lsum1 += sum1;
        __syncwarp();

        // O += P @ V (1-term): P A-frag + V B-frags via ldmatrix
        #pragma unroll
        for (int ks = 0; ks < 4; ks++) {
            uint32_t ap[4];
            ldsm_x4(ap, sPs + (basePa + ks * 16) * 2);
            #pragma unroll
            for (int nfp = 0; nfp < 4; nfp++) {
                uint32_t vq[4];
                ldsm_x4(vq, sV + oKV + (baseKV + nfp * 16 * 72 + ks * 16) * 2);
                mma16(o[nfp * 2],     ap, vq[0], vq[1]);
                mma16(o[nfp * 2 + 1], ap, vq[2], vq[3]);
            }
        }
        __syncwarp();   // Ps reads done before next tile's stores (warp-private)
    }

    // epilogue: write fp16 hi/lo in [B,N,C] for proj
    float inv0 = 1.f / lsum0, inv1 = 1.f / lsum1;
    const int bb = bh >> 4, hh = bh & 15;
    #pragma unroll
    for (int nf = 0; nf < 8; nf++) {
        int cc = nf * 8 + 2 * tig;
        size_t i0 = ((size_t)(bb * N_ + qrow0 + gid) * 1024 + hh * 64 + cc) >> 1;
        size_t i1 = ((size_t)(bb * N_ + qrow0 + gid + 8) * 1024 + hh * 64 + cc) >> 1;
        uint32_t h, l;
        splith2(o[nf][0] * inv0, o[nf][1] * inv0, h, l);
        ((uint32_t*)g_oh)[i0] = h; ((uint32_t*)g_ol)[i0] = l;
        splith2(o[nf][2] * inv1, o[nf][3] * inv1, h, l);
        ((uint32_t*)g_oh)[i1] = h; ((uint32_t*)g_ol)[i1] = l;
    }
}

// ================= launch =================
extern "C" void kernel_launch(void* const* d_in, const int* in_sizes, int n_in,
                              void* d_out, int out_size) {
    const float* x      = (const float*)d_in[0];
    const float* w_qkv  = (const float*)d_in[1];
    const float* w_proj = (const float*)d_in[2];
    const float* b_proj = (const float*)d_in[3];
    const float* qn_w   = (const float*)d_in[4];
    const float* kn_w   = (const float*)d_in[5];
    const float* fc     = (const float*)d_in[6];
    const float* fs     = (const float*)d_in[7];
    float* out = (float*)d_out;

    __half *xh, *xl, *wqkvT, *wprojT, *oh, *ol;
    cudaGetSymbolAddress((void**)&xh,     g_xh);
    cudaGetSymbolAddress((void**)&xl,     g_xl);
    cudaGetSymbolAddress((void**)&wqkvT,  g_wqkvT16);
    cudaGetSymbolAddress((void**)&wprojT, g_wprojT16);
    cudaGetSymbolAddress((void**)&oh,     g_oh);
    cudaGetSymbolAddress((void**)&ol,     g_ol);

    split_x<<<QKV_ELEMS / 512, 256>>>(x);
    transpose_w16<<<dim3(96, 32), dim3(32, 8)>>>(w_qkv, wqkvT, 1024, 3072);
    transpose_w16<<<dim3(32, 32), dim3(32, 8)>>>(w_proj, wprojT, 1024, 1024);

    const int gemm_smem = 9 * 128 * 40 * 2;   // 92160 B (Ah,Al,Bh x 3 stages)
    cudaFuncSetAttribute(gemm_f16<0>, cudaFuncAttributeMaxDynamicSharedMemorySize, gemm_smem);
    cudaFuncSetAttribute(gemm_f16<1>, cudaFuncAttributeMaxDynamicSharedMemorySize, gemm_smem);

    gemm_f16<0><<<dim3(24, 64), 256, gemm_smem>>>(xh, xl, wqkvT, nullptr, nullptr);
    norm_rope<<<32768, 256>>>(qn_w, kn_w, fc, fs);

    const int attn_smem = (6 * 64 * 72 + 8 * 16 * 72) * 2;   // 73728 B (3-stage K/V + Ps)
    cudaFuncSetAttribute(flash_attn_f16, cudaFuncAttributeMaxDynamicSharedMemorySize, attn_smem);
    flash_attn_f16<<<dim3(16, 64), 256, attn_smem>>>();

    gemm_f16<1><<<dim3(8, 64), 256, gemm_smem>>>(oh, ol, wprojT, b_proj, out);
}

// round 13
// speedup vs baseline: 6.0714x; 1.3049x over previous
#include <cuda_runtime.h>
#include <cuda_fp16.h>
#include <cstdint>

#define B_ 4
#define N_ 2048
#define C_ 1024
#define H_ 16
#define D_ 64
#define QKV_ELEMS (B_*H_*N_*D_)   // 8388608 == 8192*1024

// Scratch (allocation-free rule: __device__ globals)
__device__ float  g_q[QKV_ELEMS];          // qkv out, pre-norm fp32 [B,H,N,D]
__device__ float  g_k[QKV_ELEMS];
__device__ __half g_qh[QKV_ELEMS];         // post-norm Q hi/lo [B,H,N,D]
__device__ __half g_ql[QKV_ELEMS];
__device__ __half g_k16[QKV_ELEMS];        // post-norm K, rna fp16
__device__ __half g_vt16[QKV_ELEMS];       // V transposed [B,H,D,N], rna fp16
__device__ __half g_oh[QKV_ELEMS];         // attn out, rna fp16 [B,N,C]
__device__ __half g_xh[QKV_ELEMS];         // x rna fp16 [B*N, C]
__device__ __half g_wqkvT16[3072 * 1024];  // w_qkv^T rna fp16
__device__ __half g_wprojT16[1024 * 1024]; // w_proj^T rna fp16

// ---------------- helpers ----------------
__device__ __forceinline__ uint32_t pkh2(float lo, float hi) {
    uint32_t r; asm("cvt.rn.f16x2.f32 %0, %1, %2;" : "=r"(r) : "f"(hi), "f"(lo)); return r;
}
__device__ __forceinline__ float2 uph2(uint32_t v) {
    float2 r;
    asm("{.reg .f16 l, h;\n\t mov.b32 {l, h}, %2;\n\t cvt.f32.f16 %0, l;\n\t cvt.f32.f16 %1, h;}"
        : "=f"(r.x), "=f"(r.y) : "r"(v));
    return r;
}
// split pair (a0,a1) into packed fp16 hi and packed fp16 residual-lo
__device__ __forceinline__ void splith2(float a0, float a1, uint32_t& h, uint32_t& l) {
    h = pkh2(a0, a1);
    float2 hf = uph2(h);
    l = pkh2(a0 - hf.x, a1 - hf.y);
}
__device__ __forceinline__ float exp2a(float x) {
    float r; asm("ex2.approx.f32 %0, %1;" : "=f"(r) : "f"(x)); return r;
}
__device__ __forceinline__ uint32_t smem_u32(const void* p) {
    uint32_t a;
    asm("{ .reg .u64 t; cvta.to.shared.u64 t, %1; cvt.u32.u64 %0, t; }" : "=r"(a) : "l"(p));
    return a;
}
__device__ __forceinline__ void cp16(uint32_t dst, const void* src) {
    asm volatile("cp.async.cg.shared.global [%0], [%1], 16;" :: "r"(dst), "l"(src));
}
#define CP_COMMIT() asm volatile("cp.async.commit_group;" ::: "memory")
#define CP_WAIT(n)  asm volatile("cp.async.wait_group %0;" :: "n"(n) : "memory")

// ldmatrix x4: four 8x8 b16 matrices -> 4 u32/thread
__device__ __forceinline__ void ldsm_x4(uint32_t* r, uint32_t addr) {
    asm volatile("ldmatrix.sync.aligned.m8n8.x4.shared.b16 {%0,%1,%2,%3}, [%4];"
        : "=r"(r[0]), "=r"(r[1]), "=r"(r[2]), "=r"(r[3]) : "r"(addr));
}

// m16n8k16 fp16 mma, fp32 accum: D += A*B. A: 4 b32 (f16x2), B: 2 b32, C/D: 4 f32.
__device__ __forceinline__ void mma16(float* d, const uint32_t* a, uint32_t b0, uint32_t b1) {
    asm volatile(
        "mma.sync.aligned.m16n8k16.row.col.f32.f16.f16.f32 "
        "{%0,%1,%2,%3}, {%4,%5,%6,%7}, {%8,%9}, {%0,%1,%2,%3};"
        : "+f"(d[0]), "+f"(d[1]), "+f"(d[2]), "+f"(d[3])
        : "r"(a[0]), "r"(a[1]), "r"(a[2]), "r"(a[3]), "r"(b0), "r"(b1));
}

// ================= prep: x -> rna fp16 =================
__global__ __launch_bounds__(256) void round_x(const float* __restrict__ x) {
    int i = blockIdx.x * 256 + threadIdx.x;     // pair index
    float2 v = *(const float2*)(x + (size_t)i * 2);
    ((uint32_t*)g_xh)[i] = pkh2(v.x, v.y);
}

// ================= weight transpose: dst[c][r] = rna_fp16(src[r][c]) =================
__global__ __launch_bounds__(256) void transpose_w16(const float* __restrict__ src,
                                                     __half* __restrict__ dst,
                                                     int R, int Ccols) {
    __shared__ float t[32][33];
    int bx = blockIdx.x * 32, by = blockIdx.y * 32;
    int tx = threadIdx.x, ty = threadIdx.y;      // 32 x 8
    #pragma unroll
    for (int i = 0; i < 32; i += 8)
        t[ty + i][tx] = src[(size_t)(by + ty + i) * Ccols + bx + tx];
    __syncthreads();
    #pragma unroll
    for (int i = 0; i < 32; i += 8)
        dst[(size_t)(bx + ty + i) * R + by + tx] = __float2half_rn(t[tx][ty + i]);
}

// ================= fp16 1-term mma GEMM, 3-stage cp.async, ldmatrix frags =================
// C[M,NN] = Ah[M,1024] @ Bh[NN,1024]^T ; both operands rna fp16 (zero-mean rounding).
// BM=BN=128, BK=32 (2 k16 slabs); 8 warps, 64x32 warp tiles.
// MODE 0: qkv (q,k fp32 scatter; v -> g_vt16 transposed) ; MODE 1: proj (bias + out)
template<int MODE>
__global__ __launch_bounds__(256, 2) void gemm_f16(const __half* __restrict__ Agh,
                                                   const __half* __restrict__ Bgh,
                                                   const float* __restrict__ bias,
                                                   float* __restrict__ out) {
    extern __shared__ __half gsm[];
    __half* Ahs = gsm;                      // [3][128][40]
    __half* Bhs = gsm + 3 * 128 * 40;
    const uint32_t sAh = smem_u32(Ahs), sBh = smem_u32(Bhs);
    const int tid = threadIdx.x;
    const int wid = tid >> 5, lane = tid & 31;
    const int gid = lane >> 2, tig = lane & 3;
    const int wm = wid & 1, wn = wid >> 1;       // 2 x 4 warp grid
    const int bn = blockIdx.x, bm = blockIdx.y;

    // ldmatrix lane offsets (halves)
    const int rA = (lane & 7) + ((lane >> 3) & 1) * 8;   // A-frag row
    const int cA = ((lane >> 4) & 1) * 8;                // A-frag col
    const int rB = (lane & 7) + ((lane >> 4) & 1) * 8;   // B-frag row
    const int cB = ((lane >> 3) & 1) * 8;                // B-frag col
    const uint32_t baseA = (wm * 64 + rA) * 40 + cA;
    const uint32_t baseB = (wn * 32 + rB) * 40 + cB;

    float c[4][4][4];
    #pragma unroll
    for (int mf = 0; mf < 4; mf++)
        #pragma unroll
        for (int nf = 0; nf < 4; nf++)
            #pragma unroll
            for (int r = 0; r < 4; r++) c[mf][nf][r] = 0.f;

    const __half* Ah0 = Agh + (size_t)(bm * 128) * 1024;
    const __half* Bh0 = Bgh + (size_t)(bn * 128) * 1024;
    const int lr = tid >> 2, lc = (tid & 3) * 8;   // loader: 64 row-pairs, 8-half chunks

    auto issue = [&](int t) {
        const int buf = t % 3;
        #pragma unroll
        for (int it = 0; it < 2; it++) {
            int r = lr + it * 64;
            uint32_t so = ((buf * 128 + r) * 40 + lc) * 2;
            size_t go = (size_t)r * 1024 + t * 32 + lc;
            cp16(sAh + so, Ah0 + go);
            cp16(sBh + so, Bh0 + go);
        }
        CP_COMMIT();
    };

    issue(0); issue(1);
    for (int t = 0; t < 32; t++) {
        if (t < 31) { CP_WAIT(1); }   // pending {t, t+1} -> tile t landed
        else        { CP_WAIT(0); }
        __syncthreads();              // orders iter t-1 reads before reusing buf (t+2)%3
        if (t + 2 < 32) issue(t + 2);
        const uint32_t oT = (uint32_t)(t % 3) * (128 * 40 * 2);
        #pragma unroll
        for (int ks = 0; ks < 2; ks++) {
            uint32_t bq[8];
            ldsm_x4(bq + 0, sBh + oT + (baseB + ks * 16) * 2);
            ldsm_x4(bq + 4, sBh + oT + (baseB + 16 * 40 + ks * 16) * 2);
            #pragma unroll
            for (int mf = 0; mf < 4; mf++) {
                uint32_t ah[4];
                ldsm_x4(ah, sAh + oT + (baseA + mf * 16 * 40 + ks * 16) * 2);
                #pragma unroll
                for (int nf = 0; nf < 4; nf++)
                    mma16(c[mf][nf], ah, bq[nf * 2], bq[nf * 2 + 1]);
            }
        }
    }

    // epilogue: thread holds rows (r0, r0+8), cols (gcol, gcol+1) per fragment
    #pragma unroll
    for (int mf = 0; mf < 4; mf++) {
        int r0g = bm * 128 + wm * 64 + mf * 16 + gid;
        int r1g = r0g + 8;
        #pragma unroll
        for (int nf = 0; nf < 4; nf++) {
            int gcol = bn * 128 + wn * 32 + nf * 8 + 2 * tig;
            if (MODE == 0) {
                int which = gcol >> 10, h = (gcol >> 6) & 15, d = gcol & 63;
                int b0i = r0g >> 11, n0i = r0g & 2047;
                int b1i = r1g >> 11, n1i = r1g & 2047;
                if (which == 2) {    // v: rna fp16, transposed [B,H,D,N]
                    size_t vb0 = ((size_t)(b0i * H_ + h)) * 64;
                    size_t vb1 = ((size_t)(b1i * H_ + h)) * 64;
                    g_vt16[(vb0 + d) * 2048 + n0i]     = __float2half_rn(c[mf][nf][0]);
                    g_vt16[(vb0 + d + 1) * 2048 + n0i] = __float2half_rn(c[mf][nf][1]);
                    g_vt16[(vb1 + d) * 2048 + n1i]     = __float2half_rn(c[mf][nf][2]);
                    g_vt16[(vb1 + d + 1) * 2048 + n1i] = __float2half_rn(c[mf][nf][3]);
                } else {
                    float* dst = which == 0 ? g_q : g_k;
                    *(float2*)(dst + (((size_t)b0i * H_ + h) * N_ + n0i) * D_ + d) =
                        make_float2(c[mf][nf][0], c[mf][nf][1]);
                    *(float2*)(dst + (((size_t)b1i * H_ + h) * N_ + n1i) * D_ + d) =
                        make_float2(c[mf][nf][2], c[mf][nf][3]);
                }
            } else {
                float bx = bias[gcol], by = bias[gcol + 1];
                *(float2*)(out + (size_t)r0g * 1024 + gcol) =
                    make_float2(c[mf][nf][0] + bx, c[mf][nf][1] + by);
                *(float2*)(out + (size_t)r1g * 1024 + gcol) =
                    make_float2(c[mf][nf][2] + bx, c[mf][nf][3] + by);
            }
        }
    }
}

// ================= RMSNorm + RoPE: q -> fp16 hi/lo, k -> rna fp16 =================
__global__ __launch_bounds__(256) void norm_rope(const float* __restrict__ qn_w,
                                                 const float* __restrict__ kn_w,
                                                 const float* __restrict__ fc,
                                                 const float* __restrict__ fs) {
    int gw = (blockIdx.x * 256 + threadIdx.x) >> 5;
    int lane = threadIdx.x & 31;
    const int half = B_ * H_ * N_;
    const float* buf; const float* w; int r; bool isk;
    if (gw < half) { buf = g_q; w = qn_w; r = gw; isk = false; }
    else           { buf = g_k; w = kn_w; r = gw - half; isk = true; }
    int n = r & (N_ - 1);
    float2 v = *(const float2*)(buf + (size_t)r * D_ + lane * 2);
    float ss = v.x * v.x + v.y * v.y;
    #pragma unroll
    for (int o = 16; o; o >>= 1) ss += __shfl_xor_sync(0xffffffffu, ss, o);
    float rinv = rsqrtf(ss * (1.0f / D_) + 1e-6f);
    float a = v.x * rinv * w[lane * 2];
    float b = v.y * rinv * w[lane * 2 + 1];
    const float* fcp = fc + n * D_ + lane * 2;
    const float* fsp = fs + n * D_ + lane * 2;
    float c0 = fcp[0], c1 = fcp[1], s0 = fsp[0], s1 = fsp[1];
    float o0 = a * c0 - b * s0, o1 = b * c1 + a * s1;
    if (!isk) {
        uint32_t h, l; splith2(o0, o1, h, l);
        ((uint32_t*)g_qh)[r * 32 + lane] = h;
        ((uint32_t*)g_ql)[r * 32 + lane] = l;
    } else {
        ((uint32_t*)g_k16)[r * 32 + lane] = pkh2(o0, o1);
    }
}

// ================= flash attention, fp16 mma + ldmatrix, 3-stage, 2 CTAs/SM =================
// Grid (N/128, B*H). 256 thr, 8 warps; warp w owns q rows [qt*128+16w, +16).
// ||q||=||k||=8 after rmsnorm => |s*scale| <= 8: static softmax, no max tracking.
// l accumulates the ROUNDED P (exact reweighting). Strides 72 halves: conflict-free.
__global__ __launch_bounds__(256, 2) void flash_attn_f16() {
    extern __shared__ __half smh[];
    __half* Ks  = smh;                     // [3][64][72]
    __half* Vt  = smh + 3 * 64 * 72;       // [3][64][72]
    __half* PsB = smh + 6 * 64 * 72;       // [8][16][72]
    const uint32_t sK = smem_u32(Ks), sV = smem_u32(Vt);
    const int tid = threadIdx.x;
    const int wid = tid >> 5, lane = tid & 31;
    const int gid = lane >> 2, tig = lane & 3;
    __half* Ps = PsB + wid * 16 * 72;      // warp-private
    const uint32_t sPs = smem_u32(Ps);

    const int qt = blockIdx.x, bh = blockIdx.y;
    const int qrow0 = qt * 128 + wid * 16;
    const float SC2 = 0.125f * 1.44269504088896f;   // scale * log2(e)

    // ldmatrix lane offsets (halves)
    const int rA = (lane & 7) + ((lane >> 3) & 1) * 8;
    const int cA = ((lane >> 4) & 1) * 8;
    const int rB = (lane & 7) + ((lane >> 4) & 1) * 8;
    const int cB = ((lane >> 3) & 1) * 8;
    const uint32_t baseKV = (uint32_t)(rB * 72 + cB);
    const uint32_t basePa = (uint32_t)(rA * 72 + cA);

    // Q fragments (4 k16 slabs over D=64), hi and lo
    uint32_t aqh[4][4], aql[4][4];
    {
        const __half* Qh = g_qh + ((size_t)bh * N_ + qrow0) * 64;
        const __half* Ql = g_ql + ((size_t)bh * N_ + qrow0) * 64;
        #pragma unroll
        for (int ks = 0; ks < 4; ks++) {
            int base = gid * 64 + ks * 16 + 2 * tig;
            aqh[ks][0] = *(const uint32_t*)(Qh + base);
            aqh[ks][1] = *(const uint32_t*)(Qh + base + 8 * 64);
            aqh[ks][2] = *(const uint32_t*)(Qh + base + 8);
            aqh[ks][3] = *(const uint32_t*)(Qh + base + 8 * 64 + 8);
            aql[ks][0] = *(const uint32_t*)(Ql + base);
            aql[ks][1] = *(const uint32_t*)(Ql + base + 8 * 64);
            aql[ks][2] = *(const uint32_t*)(Ql + base + 8);
            aql[ks][3] = *(const uint32_t*)(Ql + base + 8 * 64 + 8);
        }
    }

    float lsum0 = 0.f, lsum1 = 0.f;
    float o[8][4];
    #pragma unroll
    for (int nf = 0; nf < 8; nf++)
        #pragma unroll
        for (int r = 0; r < 4; r++) o[nf][r] = 0.f;

    auto issueKV = [&](int t) {
        const int buf = t % 3;
        #pragma unroll
        for (int i = 0; i < 2; i++) {
            int cc = tid + i * 256;               // 0..511
            int r = cc >> 3, off = (cc & 7) * 8;
            cp16(sK + (((buf * 64 + r) * 72 + off) << 1),
                 g_k16 + ((size_t)bh * 2048 + t * 64 + r) * 64 + off);
            cp16(sV + (((buf * 64 + r) * 72 + off) << 1),
                 g_vt16 + ((size_t)bh * 64 + r) * 2048 + t * 64 + off);
        }
        CP_COMMIT();
    };

    issueKV(0); issueKV(1);
    for (int kt = 0; kt < N_ / 64; kt++) {
        if (kt < 31) { CP_WAIT(1); }
        else         { CP_WAIT(0); }
        __syncthreads();              // orders iter kt-1 reads before reusing buf (kt+2)%3
        if (kt + 2 < 32) issueKV(kt + 2);
        const uint32_t oKV = (uint32_t)(kt % 3) * (64 * 72 * 2);

        // S = Q @ K^T (2-term): K B-frags via ldmatrix (pairs of nf)
        float s[8][4];
        #pragma unroll
        for (int nf = 0; nf < 8; nf++)
            s[nf][0] = s[nf][1] = s[nf][2] = s[nf][3] = 0.f;
        #pragma unroll
        for (int ks = 0; ks < 4; ks++) {
            #pragma unroll
            for (int nfp = 0; nfp < 4; nfp++) {
                uint32_t kq[4];
                ldsm_x4(kq, sK + oKV + (baseKV + nfp * 16 * 72 + ks * 16) * 2);
                mma16(s[nfp * 2],     aql[ks], kq[0], kq[1]);
                mma16(s[nfp * 2],     aqh[ks], kq[0], kq[1]);
                mma16(s[nfp * 2 + 1], aql[ks], kq[2], kq[3]);
                mma16(s[nfp * 2 + 1], aqh[ks], kq[2], kq[3]);
            }
        }

        // static softmax; l from ROUNDED p
        float sum0 = 0.f, sum1 = 0.f;
        #pragma unroll
        for (int nf = 0; nf < 8; nf++) {
            float p0 = exp2a(s[nf][0] * SC2);
            float p1 = exp2a(s[nf][1] * SC2);
            float p2 = exp2a(s[nf][2] * SC2);
            float p3 = exp2a(s[nf][3] * SC2);
            uint32_t u01 = pkh2(p0, p1), u23 = pkh2(p2, p3);
            float2 r01 = uph2(u01), r23 = uph2(u23);
            sum0 += r01.x + r01.y; sum1 += r23.x + r23.y;
            *(uint32_t*)(Ps + gid * 72 + nf * 8 + 2 * tig)       = u01;
            *(uint32_t*)(Ps + (gid + 8) * 72 + nf * 8 + 2 * tig) = u23;
        }
        sum0 += __shfl_xor_sync(0xffffffffu, sum0, 1);
        sum0 += __shfl_xor_sync(0xffffffffu, sum0, 2);
        sum1 += __shfl_xor_sync(0xffffffffu, sum1, 1);
        sum1 += __shfl_xor_sync(0xffffffffu, sum1, 2);
        lsum0 += sum0;
        lsum1 += sum1;
        __syncwarp();

        // O += P @ V (1-term): P A-frag + V B-frags via ldmatrix
        #pragma unroll
        for (int ks = 0; ks < 4; ks++) {
            uint32_t ap[4];
            ldsm_x4(ap, sPs + (basePa + ks * 16) * 2);
            #pragma unroll
            for (int nfp = 0; nfp < 4; nfp++) {
                uint32_t vq[4];
                ldsm_x4(vq, sV + oKV + (baseKV + nfp * 16 * 72 + ks * 16) * 2);
                mma16(o[nfp * 2],     ap, vq[0], vq[1]);
                mma16(o[nfp * 2 + 1], ap, vq[2], vq[3]);
            }
        }
        __syncwarp();   // Ps reads done before next tile's stores (warp-private)
    }

    // epilogue: write rna fp16 in [B,N,C] for 1-term proj
    float inv0 = 1.f / lsum0, inv1 = 1.f / lsum1;
    const int bb = bh >> 4, hh = bh & 15;
    #pragma unroll
    for (int nf = 0; nf < 8; nf++) {
        int cc = nf * 8 + 2 * tig;
        size_t i0 = ((size_t)(bb * N_ + qrow0 + gid) * 1024 + hh * 64 + cc) >> 1;
        size_t i1 = ((size_t)(bb * N_ + qrow0 + gid + 8) * 1024 + hh * 64 + cc) >> 1;
        ((uint32_t*)g_oh)[i0] = pkh2(o[nf][0] * inv0, o[nf][1] * inv0);
        ((uint32_t*)g_oh)[i1] = pkh2(o[nf][2] * inv1, o[nf][3] * inv1);
    }
}

// ================= launch =================
extern "C" void kernel_launch(void* const* d_in, const int* in_sizes, int n_in,
                              void* d_out, int out_size) {
    const float* x      = (const float*)d_in[0];
    const float* w_qkv  = (const float*)d_in[1];
    const float* w_proj = (const float*)d_in[2];
    const float* b_proj = (const float*)d_in[3];
    const float* qn_w   = (const float*)d_in[4];
    const float* kn_w   = (const float*)d_in[5];
    const float* fc     = (const float*)d_in[6];
    const float* fs     = (const float*)d_in[7];
    float* out = (float*)d_out;

    __half *xh, *wqkvT, *wprojT, *oh;
    cudaGetSymbolAddress((void**)&xh,     g_xh);
    cudaGetSymbolAddress((void**)&wqkvT,  g_wqkvT16);
    cudaGetSymbolAddress((void**)&wprojT, g_wprojT16);
    cudaGetSymbolAddress((void**)&oh,     g_oh);

    round_x<<<QKV_ELEMS / 512, 256>>>(x);
    transpose_w16<<<dim3(96, 32), dim3(32, 8)>>>(w_qkv, wqkvT, 1024, 3072);
    transpose_w16<<<dim3(32, 32), dim3(32, 8)>>>(w_proj, wprojT, 1024, 1024);

    const int gemm_smem = 6 * 128 * 40 * 2;   // 61440 B (Ah,Bh x 3 stages)
    cudaFuncSetAttribute(gemm_f16<0>, cudaFuncAttributeMaxDynamicSharedMemorySize, gemm_smem);
    cudaFuncSetAttribute(gemm_f16<1>, cudaFuncAttributeMaxDynamicSharedMemorySize, gemm_smem);

    gemm_f16<0><<<dim3(24, 64), 256, gemm_smem>>>(xh, wqkvT, nullptr, nullptr);
    norm_rope<<<32768, 256>>>(qn_w, kn_w, fc, fs);

    const int attn_smem = (6 * 64 * 72 + 8 * 16 * 72) * 2;   // 73728 B (3-stage K/V + Ps)
    cudaFuncSetAttribute(flash_attn_f16, cudaFuncAttributeMaxDynamicSharedMemorySize, attn_smem);
    flash_attn_f16<<<dim3(16, 64), 256, attn_smem>>>();

    gemm_f16<1><<<dim3(8, 64), 256, gemm_smem>>>(oh, wprojT, b_proj, out);
}